// round 5
// baseline (speedup 1.0000x reference)
#include <cuda_runtime.h>
#include <mma.h>
#include <math_constants.h>
#include <cstdint>
#include <cstddef>

using namespace nvcuda;

// ---------------------------------------------------------------------------
// Problem constants
// ---------------------------------------------------------------------------
namespace cfg {
constexpr int Bb   = 4;
constexpr int Ls   = 2048;
constexpr int Din  = 512;
constexpr int Hh   = 8;
constexpr int Dh   = 64;
constexpr int Dmid = 2048;
constexpr int Mtok = Bb * Ls;   // 8192 tokens
}

// ---------------------------------------------------------------------------
// Scratch (static device globals — no allocations anywhere)
// ---------------------------------------------------------------------------
__device__ float g_Q[cfg::Bb * cfg::Hh * cfg::Ls * cfg::Dh];   // [b,h,l,d]
__device__ float g_K[cfg::Bb * cfg::Hh * cfg::Ls * cfg::Dh];
__device__ float g_V[cfg::Bb * cfg::Hh * cfg::Ls * cfg::Dh];
__device__ float g_attn[cfg::Mtok * cfg::Din];                 // concat [tok, h*64+d]
__device__ float g_proj[cfg::Mtok * cfg::Din];
__device__ float g_h1[cfg::Mtok * cfg::Din];
__device__ float g_mid[cfg::Mtok * cfg::Dmid];
__device__ float g_ff[cfg::Mtok * cfg::Din];

// ---------------------------------------------------------------------------
// cp.async helpers (LDGSTS)
// ---------------------------------------------------------------------------
__device__ __forceinline__ void cpa16(void* smem, const void* gmem) {
    unsigned sa = (unsigned)__cvta_generic_to_shared(smem);
    asm volatile("cp.async.cg.shared.global [%0], [%1], 16;" :: "r"(sa), "l"(gmem));
}
__device__ __forceinline__ void cpa_commit() {
    asm volatile("cp.async.commit_group;");
}
template <int N>
__device__ __forceinline__ void cpa_wait() {
    asm volatile("cp.async.wait_group %0;" :: "n"(N));
}

template <class Frag>
__device__ __forceinline__ void to_tf32(Frag& f) {
#pragma unroll
    for (int i = 0; i < f.num_elements; i++) f.x[i] = wmma::__float_to_tf32(f.x[i]);
}

// ---------------------------------------------------------------------------
// Generic tf32 GEMM: C[M,N] = A[M,K] * B[K,N], fp32 in/out, fp32 accum.
// Block tile 128x128x16, 256 threads (8 warps, 2x4), warp tile 64x32.
// Epilogues: 0 = plain fp32, 1 = relu, 2 = QKV head-split layout [b,h,l,64].
// ---------------------------------------------------------------------------
constexpr int BM = 128, BN = 128, BK = 16;
constexpr int APAD = 4, BPAD = 4;

template <int EPI>
__global__ __launch_bounds__(256) void gemm_tf32(
    const float* __restrict__ A, const float* __restrict__ Bw,
    float* __restrict__ C, int M, int N, int K)
{
    __shared__ float As[2][BM][BK + APAD];   // 2*128*20*4 = 20.5 KB
    __shared__ float Bs[2][BK][BN + BPAD];   // 2*16*132*4 = 16.9 KB

    const int tid  = threadIdx.x;
    const int bm   = blockIdx.y * BM;
    const int bn   = blockIdx.x * BN;
    const int warp = tid >> 5;
    const int lane = tid & 31;
    const int wr   = warp >> 2;   // 0..1
    const int wc   = warp & 3;    // 0..3

    wmma::fragment<wmma::accumulator, 16, 16, 8, float> acc[4][2];
#pragma unroll
    for (int mi = 0; mi < 4; mi++)
#pragma unroll
        for (int ni = 0; ni < 2; ni++) wmma::fill_fragment(acc[mi][ni], 0.0f);

    auto load_tiles = [&](int buf, int kt) {
        const int k0 = kt * BK;
        // A tile: 128 x 16 floats = 512 float4, 2 per thread
#pragma unroll
        for (int i = 0; i < 2; i++) {
            int lin = tid + i * 256;          // 0..511
            int r   = lin >> 2;
            int c4  = (lin & 3) * 4;
            cpa16(&As[buf][r][c4], A + (size_t)(bm + r) * K + k0 + c4);
        }
        // B tile: 16 x 128 floats = 512 float4
#pragma unroll
        for (int i = 0; i < 2; i++) {
            int lin = tid + i * 256;
            int r   = lin >> 5;
            int c4  = (lin & 31) * 4;
            cpa16(&Bs[buf][r][c4], Bw + (size_t)(k0 + r) * N + bn + c4);
        }
        cpa_commit();
    };

    const int nkt = K / BK;
    load_tiles(0, 0);
    int cur = 0;
    for (int kt = 0; kt < nkt; kt++) {
        if (kt + 1 < nkt) {
            load_tiles(cur ^ 1, kt + 1);
            cpa_wait<1>();
        } else {
            cpa_wait<0>();
        }
        __syncthreads();

#pragma unroll
        for (int ks = 0; ks < 2; ks++) {
            wmma::fragment<wmma::matrix_a, 16, 16, 8, wmma::precision::tf32, wmma::row_major> af[4];
            wmma::fragment<wmma::matrix_b, 16, 16, 8, wmma::precision::tf32, wmma::row_major> bf[2];
#pragma unroll
            for (int mi = 0; mi < 4; mi++) {
                wmma::load_matrix_sync(af[mi], &As[cur][wr * 64 + mi * 16][ks * 8], BK + APAD);
                to_tf32(af[mi]);
            }
#pragma unroll
            for (int ni = 0; ni < 2; ni++) {
                wmma::load_matrix_sync(bf[ni], &Bs[cur][ks * 8][wc * 32 + ni * 16], BN + BPAD);
                to_tf32(bf[ni]);
            }
#pragma unroll
            for (int mi = 0; mi < 4; mi++)
#pragma unroll
                for (int ni = 0; ni < 2; ni++)
                    wmma::mma_sync(acc[mi][ni], af[mi], bf[ni], acc[mi][ni]);
        }
        __syncthreads();
        cur ^= 1;
    }

    // Epilogue via per-warp smem staging (reuses As; all warps passed the final sync)
    float* stg = &As[0][0][0] + warp * (16 * 20);
#pragma unroll
    for (int mi = 0; mi < 4; mi++) {
#pragma unroll
        for (int ni = 0; ni < 2; ni++) {
            wmma::store_matrix_sync(stg, acc[mi][ni], 20, wmma::mem_row_major);
            __syncwarp();
#pragma unroll
            for (int e = 0; e < 8; e++) {
                int idx = lane + e * 32;
                int r = idx >> 4, c = idx & 15;
                int gr = bm + wr * 64 + mi * 16 + r;
                int gc = bn + wc * 32 + ni * 16 + c;
                float v = stg[r * 20 + c];
                if (EPI == 1) v = fmaxf(v, 0.0f);
                if (EPI == 2) {
                    int b = gr >> 11;              // Ls = 2048
                    int l = gr & (cfg::Ls - 1);
                    int h = gc >> 6;               // Dh = 64
                    int d = gc & 63;
                    C[(((size_t)(b * cfg::Hh + h) * cfg::Ls + l) << 6) + d] = v;
                } else {
                    C[(size_t)gr * N + gc] = v;
                }
            }
            __syncwarp();
        }
    }
}

// ---------------------------------------------------------------------------
// Flash attention: one block per (b, h, q-tile of 64). 128 threads (4 warps).
// S = Q K^T * 0.125 + mask ; online softmax ; O += P V (tf32 wmma).
// Output written in concat layout [b, l, h*64 + d] fp32.
// ---------------------------------------------------------------------------
constexpr int FQ = 64, FKT = 64, FP = 68;   // padded row stride (mult of 4)
constexpr size_t FLASH_SMEM = (size_t)(6 * FQ * FP + 3 * FQ) * sizeof(float); // 105,216 B

__global__ __launch_bounds__(128) void flash_kernel(
    const float* __restrict__ Qg, const float* __restrict__ Kg,
    const float* __restrict__ Vg, const float* __restrict__ maskg,
    float* __restrict__ Og)
{
    extern __shared__ float smf[];
    float* Qs = smf;
    float* Ks = Qs + FQ * FP;
    float* Vs = Ks + FKT * FP;
    float* Ss = Vs + FKT * FP;
    float* Os = Ss + FQ * FP;
    float* Ts = Os + FQ * FP;
    float* mrow = Ts + FQ * FP;
    float* lrow = mrow + FQ;
    float* frow = lrow + FQ;

    const int tid  = threadIdx.x;
    const int warp = tid >> 5;
    const int b    = blockIdx.z;
    const int h    = blockIdx.y;
    const int q0   = blockIdx.x * FQ;

    const float* Qbase = Qg + ((size_t)(b * cfg::Hh + h) * cfg::Ls + q0) * cfg::Dh;
#pragma unroll
    for (int i = 0; i < 8; i++) {
        int f4 = tid + i * 128;
        int r = f4 >> 4, c = (f4 & 15) * 4;
        *(float4*)&Qs[r * FP + c] = *(const float4*)&Qbase[r * cfg::Dh + c];
    }
#pragma unroll
    for (int i = 0; i < 32; i++) {
        int lin = tid + i * 128;
        Os[(lin >> 6) * FP + (lin & 63)] = 0.0f;
    }
    if (tid < FQ) { mrow[tid] = -CUDART_INF_F; lrow[tid] = 0.0f; }
    __syncthreads();

    for (int kt = 0; kt < cfg::Ls / FKT; kt++) {
        const int k0 = kt * FKT;
        const float* Kbase = Kg + ((size_t)(b * cfg::Hh + h) * cfg::Ls + k0) * cfg::Dh;
        const float* Vbase = Vg + ((size_t)(b * cfg::Hh + h) * cfg::Ls + k0) * cfg::Dh;
#pragma unroll
        for (int i = 0; i < 8; i++) {
            int f4 = tid + i * 128;
            int r = f4 >> 4, c = (f4 & 15) * 4;
            *(float4*)&Ks[r * FP + c] = *(const float4*)&Kbase[r * cfg::Dh + c];
            *(float4*)&Vs[r * FP + c] = *(const float4*)&Vbase[r * cfg::Dh + c];
        }
        __syncthreads();

        // ---- S = Q K^T : each warp computes rows [warp*16, warp*16+16) ----
        {
            wmma::fragment<wmma::accumulator, 16, 16, 8, float> acc[4];
#pragma unroll
            for (int n = 0; n < 4; n++) wmma::fill_fragment(acc[n], 0.0f);
#pragma unroll
            for (int kk = 0; kk < 8; kk++) {
                wmma::fragment<wmma::matrix_a, 16, 16, 8, wmma::precision::tf32, wmma::row_major> af;
                wmma::load_matrix_sync(af, &Qs[warp * 16 * FP + kk * 8], FP);
                to_tf32(af);
#pragma unroll
                for (int n = 0; n < 4; n++) {
                    wmma::fragment<wmma::matrix_b, 16, 16, 8, wmma::precision::tf32, wmma::col_major> bf;
                    wmma::load_matrix_sync(bf, &Ks[(n * 16) * FP + kk * 8], FP);
                    to_tf32(bf);
                    wmma::mma_sync(acc[n], af, bf, acc[n]);
                }
            }
#pragma unroll
            for (int n = 0; n < 4; n++)
                wmma::store_matrix_sync(&Ss[warp * 16 * FP + n * 16], acc[n], FP, wmma::mem_row_major);
        }
        __syncthreads();

        // ---- online softmax: 2 threads per row, 32 cols each ----
        {
            const int r  = tid >> 1;
            const int hf = tid & 1;
            const float* mk = maskg + ((size_t)b * cfg::Ls + q0 + r) * cfg::Ls + k0 + hf * 32;
            float* srow = &Ss[r * FP + hf * 32];
            float vals[32];
            float mx = -CUDART_INF_F;
#pragma unroll
            for (int c = 0; c < 32; c++) {
                float v = srow[c] * 0.125f + mk[c];
                vals[c] = v;
                mx = fmaxf(mx, v);
            }
            mx = fmaxf(mx, __shfl_xor_sync(0xffffffffu, mx, 1));
            float mold = mrow[r];
            float mnew = fmaxf(mold, mx);
            float corr = __expf(mold - mnew);
            float s = 0.0f;
#pragma unroll
            for (int c = 0; c < 32; c++) {
                float p = __expf(vals[c] - mnew);
                srow[c] = p;
                s += p;
            }
            s += __shfl_xor_sync(0xffffffffu, s, 1);
            if (hf == 0) {
                lrow[r] = lrow[r] * corr + s;
                mrow[r] = mnew;
                frow[r] = corr;
            }
        }
        __syncthreads();

        // ---- T = P V ----
        {
            wmma::fragment<wmma::accumulator, 16, 16, 8, float> acc[4];
#pragma unroll
            for (int n = 0; n < 4; n++) wmma::fill_fragment(acc[n], 0.0f);
#pragma unroll
            for (int kk = 0; kk < 8; kk++) {
                wmma::fragment<wmma::matrix_a, 16, 16, 8, wmma::precision::tf32, wmma::row_major> af;
                wmma::load_matrix_sync(af, &Ss[warp * 16 * FP + kk * 8], FP);
                to_tf32(af);
#pragma unroll
                for (int n = 0; n < 4; n++) {
                    wmma::fragment<wmma::matrix_b, 16, 16, 8, wmma::precision::tf32, wmma::row_major> bf;
                    wmma::load_matrix_sync(bf, &Vs[(kk * 8) * FP + n * 16], FP);
                    to_tf32(bf);
                    wmma::mma_sync(acc[n], af, bf, acc[n]);
                }
            }
#pragma unroll
            for (int n = 0; n < 4; n++)
                wmma::store_matrix_sync(&Ts[warp * 16 * FP + n * 16], acc[n], FP, wmma::mem_row_major);
        }
        __syncthreads();

        // ---- O = O * corr + T ----
#pragma unroll
        for (int i = 0; i < 32; i++) {
            int lin = tid + i * 128;
            int r = lin >> 6, c = lin & 63;
            Os[r * FP + c] = Os[r * FP + c] * frow[r] + Ts[r * FP + c];
        }
        __syncthreads();
    }

    // ---- normalize & write concat layout [b, l, h*64 + d] ----
#pragma unroll
    for (int i = 0; i < 32; i++) {
        int lin = tid + i * 128;
        int r = lin >> 6, c = lin & 63;
        Og[((size_t)b * cfg::Ls + q0 + r) * cfg::Din + h * cfg::Dh + c] =
            Os[r * FP + c] / lrow[r];
    }
}

// ---------------------------------------------------------------------------
// Fused residual-add + LayerNorm over last dim (512). One block per row.
// ---------------------------------------------------------------------------
__global__ __launch_bounds__(128) void ln_add_kernel(
    const float* __restrict__ x, const float* __restrict__ y, float* __restrict__ out)
{
    const int row = blockIdx.x;
    const float* px = x + (size_t)row * cfg::Din;
    const float* py = y + (size_t)row * cfg::Din;

    float v[4];
    float s = 0.0f, sq = 0.0f;
#pragma unroll
    for (int i = 0; i < 4; i++) {
        int c = threadIdx.x + i * 128;
        v[i] = px[c] + py[c];
        s  += v[i];
        sq += v[i] * v[i];
    }
#pragma unroll
    for (int o = 16; o > 0; o >>= 1) {
        s  += __shfl_xor_sync(0xffffffffu, s, o);
        sq += __shfl_xor_sync(0xffffffffu, sq, o);
    }
    __shared__ float ws[4], wq[4];
    __shared__ float mean_s, inv_s;
    const int warp = threadIdx.x >> 5, lane = threadIdx.x & 31;
    if (lane == 0) { ws[warp] = s; wq[warp] = sq; }
    __syncthreads();
    if (threadIdx.x == 0) {
        float S = ws[0] + ws[1] + ws[2] + ws[3];
        float Q = wq[0] + wq[1] + wq[2] + wq[3];
        float mean = S * (1.0f / cfg::Din);
        float var  = Q * (1.0f / cfg::Din) - mean * mean;
        mean_s = mean;
        inv_s  = rsqrtf(var + 1e-5f);
    }
    __syncthreads();
    float* po = out + (size_t)row * cfg::Din;
#pragma unroll
    for (int i = 0; i < 4; i++) {
        int c = threadIdx.x + i * 128;
        po[c] = (v[i] - mean_s) * inv_s;
    }
}

// ---------------------------------------------------------------------------
// kernel_launch
// ---------------------------------------------------------------------------
extern "C" void kernel_launch(void* const* d_in, const int* in_sizes, int n_in,
                              void* d_out, int out_size)
{
    const float* query = (const float*)d_in[0];
    const float* key   = (const float*)d_in[1];
    const float* value = (const float*)d_in[2];
    const float* mask  = (const float*)d_in[3];
    const float* WQ    = (const float*)d_in[4];
    const float* WK    = (const float*)d_in[5];
    const float* WV    = (const float*)d_in[6];
    const float* WO    = (const float*)d_in[7];
    const float* W1    = (const float*)d_in[8];
    const float* W2    = (const float*)d_in[9];
    float* out = (float*)d_out;

    float *Qd, *Kd, *Vd, *attn, *proj, *h1, *mid, *ff;
    cudaGetSymbolAddress((void**)&Qd,   g_Q);
    cudaGetSymbolAddress((void**)&Kd,   g_K);
    cudaGetSymbolAddress((void**)&Vd,   g_V);
    cudaGetSymbolAddress((void**)&attn, g_attn);
    cudaGetSymbolAddress((void**)&proj, g_proj);
    cudaGetSymbolAddress((void**)&h1,   g_h1);
    cudaGetSymbolAddress((void**)&mid,  g_mid);
    cudaGetSymbolAddress((void**)&ff,   g_ff);

    cudaFuncSetAttribute(flash_kernel, cudaFuncAttributeMaxDynamicSharedMemorySize,
                         (int)FLASH_SMEM);

    const dim3 gProj(cfg::Din / BN, cfg::Mtok / BM);   // (4, 64)
    const dim3 gFfn1(cfg::Dmid / BN, cfg::Mtok / BM);  // (16, 64)

    // QKV projections (head-split epilogue)
    gemm_tf32<2><<<gProj, 256>>>(query, WQ, Qd, cfg::Mtok, cfg::Din, cfg::Din);
    gemm_tf32<2><<<gProj, 256>>>(key,   WK, Kd, cfg::Mtok, cfg::Din, cfg::Din);
    gemm_tf32<2><<<gProj, 256>>>(value, WV, Vd, cfg::Mtok, cfg::Din, cfg::Din);

    // Flash attention
    dim3 gFlash(cfg::Ls / FQ, cfg::Hh, cfg::Bb);       // (32, 8, 4)
    flash_kernel<<<gFlash, 128, FLASH_SMEM>>>(Qd, Kd, Vd, mask, attn);

    // Output projection + residual LN
    gemm_tf32<0><<<gProj, 256>>>(attn, WO, proj, cfg::Mtok, cfg::Din, cfg::Din);
    ln_add_kernel<<<cfg::Mtok, 128>>>(query, proj, h1);

    // FFN
    gemm_tf32<1><<<gFfn1, 256>>>(h1,  W1, mid, cfg::Mtok, cfg::Dmid, cfg::Din);
    gemm_tf32<0><<<gProj, 256>>>(mid, W2, ff,  cfg::Mtok, cfg::Din, cfg::Dmid);
    ln_add_kernel<<<cfg::Mtok, 128>>>(h1, ff, out);

    (void)in_sizes; (void)n_in; (void)out_size;
}

// round 9
// speedup vs baseline: 2.8525x; 2.8525x over previous
#include <cuda_runtime.h>
#include <mma.h>
#include <math_constants.h>
#include <cstdint>
#include <cstddef>

using namespace nvcuda;

// ---------------------------------------------------------------------------
// Problem constants
// ---------------------------------------------------------------------------
namespace cfg {
constexpr int Bb   = 4;
constexpr int Ls   = 2048;
constexpr int Din  = 512;
constexpr int Hh   = 8;
constexpr int Dh   = 64;
constexpr int Dmid = 2048;
constexpr int Mtok = Bb * Ls;   // 8192 tokens
}

// ---------------------------------------------------------------------------
// Scratch (static device globals — no allocations anywhere)
// ---------------------------------------------------------------------------
__device__ float g_Q[cfg::Bb * cfg::Hh * cfg::Ls * cfg::Dh];   // [b,h,l,d]
__device__ float g_K[cfg::Bb * cfg::Hh * cfg::Ls * cfg::Dh];
__device__ float g_V[cfg::Bb * cfg::Hh * cfg::Ls * cfg::Dh];
__device__ float g_attn[cfg::Mtok * cfg::Din];                 // concat [tok, h*64+d]
__device__ float g_proj[cfg::Mtok * cfg::Din];
__device__ float g_h1[cfg::Mtok * cfg::Din];
__device__ float g_mid[cfg::Mtok * cfg::Dmid];
__device__ float g_ff[cfg::Mtok * cfg::Din];

// ---------------------------------------------------------------------------
// cp.async helpers
// ---------------------------------------------------------------------------
__device__ __forceinline__ void cpa16(void* smem, const void* gmem) {
    unsigned sa = (unsigned)__cvta_generic_to_shared(smem);
    asm volatile("cp.async.cg.shared.global [%0], [%1], 16;" :: "r"(sa), "l"(gmem));
}
__device__ __forceinline__ void cpa_commit() {
    asm volatile("cp.async.commit_group;");
}
template <int N>
__device__ __forceinline__ void cpa_wait() {
    asm volatile("cp.async.wait_group %0;" :: "n"(N));
}

__device__ __forceinline__ unsigned f2tf(float f) {
    unsigned u;
    asm("cvt.rna.tf32.f32 %0, %1;" : "=r"(u) : "f"(f));
    return u;
}

// mma.m16n8k8 tf32: A 4 regs, B 2 regs, C/D 4 floats (in-place accumulate)
__device__ __forceinline__ void mma_tf32_16n8k8(float d[4], const unsigned a[4],
                                                const unsigned b[2]) {
    asm volatile(
        "mma.sync.aligned.m16n8k8.row.col.f32.tf32.tf32.f32 "
        "{%0,%1,%2,%3}, {%4,%5,%6,%7}, {%8,%9}, {%0,%1,%2,%3};"
        : "+f"(d[0]), "+f"(d[1]), "+f"(d[2]), "+f"(d[3])
        : "r"(a[0]), "r"(a[1]), "r"(a[2]), "r"(a[3]), "r"(b[0]), "r"(b[1]));
}

template <class Frag>
__device__ __forceinline__ void to_tf32(Frag& f) {
#pragma unroll
    for (int i = 0; i < f.num_elements; i++) f.x[i] = wmma::__float_to_tf32(f.x[i]);
}

// ---------------------------------------------------------------------------
// Generic tf32 GEMM: C[M,N] = A[M,K] * B[K,N], fp32 in/out, fp32 accum.
// Block tile 128x128x16, 256 threads (8 warps), warp tile 64x32.
// Epilogues: 0 = plain fp32, 1 = relu, 2 = QKV head-split layout [b,h,l,64].
// ---------------------------------------------------------------------------
constexpr int BM = 128, BN = 128, BK = 16;
constexpr int APAD = 4, BPAD = 4;

template <int EPI>
__device__ __forceinline__ void gemm_dev(
    const float* __restrict__ A, const float* __restrict__ Bw,
    float* __restrict__ C, int M, int N, int K)
{
    __shared__ float As[2][BM][BK + APAD];
    __shared__ float Bs[2][BK][BN + BPAD];

    const int tid  = threadIdx.x;
    const int bm   = blockIdx.y * BM;
    const int bn   = blockIdx.x * BN;
    const int warp = tid >> 5;
    const int lane = tid & 31;
    const int wr   = warp >> 2;   // 0..1
    const int wc   = warp & 3;    // 0..3

    wmma::fragment<wmma::accumulator, 16, 16, 8, float> acc[4][2];
#pragma unroll
    for (int mi = 0; mi < 4; mi++)
#pragma unroll
        for (int ni = 0; ni < 2; ni++) wmma::fill_fragment(acc[mi][ni], 0.0f);

    auto load_tiles = [&](int buf, int kt) {
        const int k0 = kt * BK;
#pragma unroll
        for (int i = 0; i < 2; i++) {
            int lin = tid + i * 256;
            int r   = lin >> 2;
            int c4  = (lin & 3) * 4;
            cpa16(&As[buf][r][c4], A + (size_t)(bm + r) * K + k0 + c4);
        }
#pragma unroll
        for (int i = 0; i < 2; i++) {
            int lin = tid + i * 256;
            int r   = lin >> 5;
            int c4  = (lin & 31) * 4;
            cpa16(&Bs[buf][r][c4], Bw + (size_t)(k0 + r) * N + bn + c4);
        }
        cpa_commit();
    };

    const int nkt = K / BK;
    load_tiles(0, 0);
    int cur = 0;
    for (int kt = 0; kt < nkt; kt++) {
        if (kt + 1 < nkt) {
            load_tiles(cur ^ 1, kt + 1);
            cpa_wait<1>();
        } else {
            cpa_wait<0>();
        }
        __syncthreads();

#pragma unroll
        for (int ks = 0; ks < 2; ks++) {
            wmma::fragment<wmma::matrix_a, 16, 16, 8, wmma::precision::tf32, wmma::row_major> af[4];
            wmma::fragment<wmma::matrix_b, 16, 16, 8, wmma::precision::tf32, wmma::row_major> bf[2];
#pragma unroll
            for (int mi = 0; mi < 4; mi++) {
                wmma::load_matrix_sync(af[mi], &As[cur][wr * 64 + mi * 16][ks * 8], BK + APAD);
                to_tf32(af[mi]);
            }
#pragma unroll
            for (int ni = 0; ni < 2; ni++) {
                wmma::load_matrix_sync(bf[ni], &Bs[cur][ks * 8][wc * 32 + ni * 16], BN + BPAD);
                to_tf32(bf[ni]);
            }
#pragma unroll
            for (int mi = 0; mi < 4; mi++)
#pragma unroll
                for (int ni = 0; ni < 2; ni++)
                    wmma::mma_sync(acc[mi][ni], af[mi], bf[ni], acc[mi][ni]);
        }
        __syncthreads();
        cur ^= 1;
    }

    float* stg = &As[0][0][0] + warp * (16 * 20);
#pragma unroll
    for (int mi = 0; mi < 4; mi++) {
#pragma unroll
        for (int ni = 0; ni < 2; ni++) {
            wmma::store_matrix_sync(stg, acc[mi][ni], 20, wmma::mem_row_major);
            __syncwarp();
#pragma unroll
            for (int e = 0; e < 8; e++) {
                int idx = lane + e * 32;
                int r = idx >> 4, c = idx & 15;
                int gr = bm + wr * 64 + mi * 16 + r;
                int gc = bn + wc * 32 + ni * 16 + c;
                float v = stg[r * 20 + c];
                if (EPI == 1) v = fmaxf(v, 0.0f);
                if (EPI == 2) {
                    int b = gr >> 11;
                    int l = gr & (cfg::Ls - 1);
                    int h = gc >> 6;
                    int d = gc & 63;
                    C[(((size_t)(b * cfg::Hh + h) * cfg::Ls + l) << 6) + d] = v;
                } else {
                    C[(size_t)gr * N + gc] = v;
                }
            }
            __syncwarp();
        }
    }
}

template <int EPI>
__global__ __launch_bounds__(256) void gemm_tf32(
    const float* __restrict__ A, const float* __restrict__ Bw,
    float* __restrict__ C, int M, int N, int K)
{
    gemm_dev<EPI>(A, Bw, C, M, N, K);
}

// Fused QKV projection: blockIdx.z selects (input, weight, output) triple.
__global__ __launch_bounds__(256) void gemm_qkv(
    const float* __restrict__ q, const float* __restrict__ k,
    const float* __restrict__ v,
    const float* __restrict__ WQ, const float* __restrict__ WK,
    const float* __restrict__ WV,
    float* __restrict__ Qd, float* __restrict__ Kd, float* __restrict__ Vd)
{
    const int z = blockIdx.z;
    const float* A = (z == 0) ? q : (z == 1) ? k : v;
    const float* W = (z == 0) ? WQ : (z == 1) ? WK : WV;
    float* C       = (z == 0) ? Qd : (z == 1) ? Kd : Vd;
    gemm_dev<2>(A, W, C, cfg::Mtok, cfg::Din, cfg::Din);
}

// ---------------------------------------------------------------------------
// Flash attention v2: raw mma.m16n8k8.tf32, S and O register-resident.
// Block = (b, h, 128 q-rows); 256 threads (8 warps), warp owns 16 rows.
// K/V double-buffered cp.async; tiles converted to tf32 in smem once.
// P (=softmax(S)) A-fragments built from S accumulators via warp shuffles
// (no smem staging).
//
// Strides: must be >= 64 (row width). 68 % 32 == 4 makes Q/K fragment loads
// conflict-free (bank = (4g+q)%32, all distinct); 72 % 32 == 8 makes the V
// B-fragment loads conflict-free (bank = (8q+g)%32, all distinct).
// ---------------------------------------------------------------------------
constexpr int FQ2  = 128;
constexpr int QSTR = 68;
constexpr int KSTR = 68;
constexpr int VSTR = 72;

constexpr int SM_Q = 0;                        // 128*68 = 8704 floats
constexpr int SM_K = SM_Q + FQ2 * QSTR;        // 2 * 64*68 = 8704
constexpr int SM_V = SM_K + 2 * 64 * KSTR;     // 2 * 64*72 = 9216
constexpr int FLASH2_FLOATS = SM_V + 2 * 64 * VSTR;           // 26624
constexpr size_t FLASH2_SMEM = (size_t)FLASH2_FLOATS * sizeof(float);  // 106,496 B

__global__ __launch_bounds__(256, 2) void flash2_kernel(
    const float* __restrict__ Qg, const float* __restrict__ Kg,
    const float* __restrict__ Vg, const float* __restrict__ maskg,
    float* __restrict__ Og)
{
    extern __shared__ float sm[];
    float* Qs = sm + SM_Q;
    float* Ks = sm + SM_K;
    float* Vs = sm + SM_V;

    const int tid  = threadIdx.x;
    const int warp = tid >> 5;
    const int lane = tid & 31;
    const int g    = lane >> 2;     // fragment row group (0..7)
    const int q    = lane & 3;      // thread-in-group (0..3)
    const int b    = blockIdx.z;
    const int h    = blockIdx.y;
    const int q0   = blockIdx.x * FQ2;
    const int wrow = warp * 16;

    const size_t bh = (size_t)(b * cfg::Hh + h) * cfg::Ls;
    const float* Qbase = Qg + (bh + q0) * cfg::Dh;

    // Q: 128 rows x 16 float4 via cp.async
#pragma unroll
    for (int i = 0; i < 8; i++) {
        int lin = tid + i * 256;
        int r = lin >> 4, c4 = (lin & 15) * 4;
        cpa16(&Qs[r * QSTR + c4], Qbase + r * cfg::Dh + c4);
    }

    auto loadKV = [&](int buf, int kt) {
        const float* Kb = Kg + (bh + kt * 64) * cfg::Dh;
        const float* Vb = Vg + (bh + kt * 64) * cfg::Dh;
#pragma unroll
        for (int i = 0; i < 4; i++) {
            int lin = tid + i * 256;
            int r = lin >> 4, c4 = (lin & 15) * 4;
            cpa16(&Ks[buf * 64 * KSTR + r * KSTR + c4], Kb + r * cfg::Dh + c4);
            cpa16(&Vs[buf * 64 * VSTR + r * VSTR + c4], Vb + r * cfg::Dh + c4);
        }
    };
    loadKV(0, 0);
    cpa_commit();

    // Register state: rows (wrow+g) and (wrow+g+8)
    float m0 = -CUDART_INF_F, m1 = -CUDART_INF_F;
    float l0 = 0.0f, l1 = 0.0f;
    float o[8][4];
#pragma unroll
    for (int t = 0; t < 8; t++)
#pragma unroll
        for (int e = 0; e < 4; e++) o[t][e] = 0.0f;

    const float* mrow0 = maskg + ((size_t)b * cfg::Ls + q0 + wrow + g) * cfg::Ls;
    const float* mrow1 = mrow0 + 8 * (size_t)cfg::Ls;

    const unsigned* Qu = (const unsigned*)Qs;
    const int srcA = (lane & 28) | (q >> 1);   // owner of P col q within quad
    const int srcB = srcA + 2;                 // owner of P col q+4
    const bool odd = (q & 1) != 0;

    for (int kt = 0; kt < cfg::Ls / 64; kt++) {
        const int cur = kt & 1;
        cpa_wait<0>();
        __syncthreads();
        if (kt + 1 < cfg::Ls / 64) { loadKV(cur ^ 1, kt + 1); cpa_commit(); }

        // Convert current K/V tiles (and Q once) to tf32 bits, in place.
        unsigned* Ku = (unsigned*)(Ks + cur * 64 * KSTR);
        unsigned* Vu = (unsigned*)(Vs + cur * 64 * VSTR);
#pragma unroll
        for (int i = 0; i < 16; i++) {
            int lin = tid + i * 256;               // 0..4095
            int r = lin >> 6, c = lin & 63;
            Ku[r * KSTR + c] = f2tf(__uint_as_float(Ku[r * KSTR + c]));
            Vu[r * VSTR + c] = f2tf(__uint_as_float(Vu[r * VSTR + c]));
        }
        if (kt == 0) {
            unsigned* Qm = (unsigned*)Qs;
#pragma unroll
            for (int i = 0; i < 32; i++) {
                int lin = tid + i * 256;           // 0..8191
                int r = lin >> 6, c = lin & 63;
                Qm[r * QSTR + c] = f2tf(__uint_as_float(Qm[r * QSTR + c]));
            }
        }
        __syncthreads();

        // ---- S = Q K^T (registers) ----
        float s[8][4];
#pragma unroll
        for (int t = 0; t < 8; t++)
#pragma unroll
            for (int e = 0; e < 4; e++) s[t][e] = 0.0f;

#pragma unroll
        for (int j = 0; j < 8; j++) {              // k over dh
            unsigned a[4];
            a[0] = Qu[(wrow + g) * QSTR + j * 8 + q];
            a[1] = Qu[(wrow + g + 8) * QSTR + j * 8 + q];
            a[2] = Qu[(wrow + g) * QSTR + j * 8 + q + 4];
            a[3] = Qu[(wrow + g + 8) * QSTR + j * 8 + q + 4];
#pragma unroll
            for (int t = 0; t < 8; t++) {          // n over kv rows
                unsigned bf[2];
                bf[0] = Ku[(t * 8 + g) * KSTR + j * 8 + q];
                bf[1] = Ku[(t * 8 + g) * KSTR + j * 8 + q + 4];
                mma_tf32_16n8k8(s[t], a, bf);
            }
        }

        // ---- scale + mask ----
        const int kcol = kt * 64;
#pragma unroll
        for (int t = 0; t < 8; t++) {
            float2 mk0 = *(const float2*)(mrow0 + kcol + t * 8 + 2 * q);
            float2 mk1 = *(const float2*)(mrow1 + kcol + t * 8 + 2 * q);
            s[t][0] = s[t][0] * 0.125f + mk0.x;
            s[t][1] = s[t][1] * 0.125f + mk0.y;
            s[t][2] = s[t][2] * 0.125f + mk1.x;
            s[t][3] = s[t][3] * 0.125f + mk1.y;
        }

        // ---- online softmax (register + 2 shfl per row) ----
        float mx0 = -CUDART_INF_F, mx1 = -CUDART_INF_F;
#pragma unroll
        for (int t = 0; t < 8; t++) {
            mx0 = fmaxf(mx0, fmaxf(s[t][0], s[t][1]));
            mx1 = fmaxf(mx1, fmaxf(s[t][2], s[t][3]));
        }
        mx0 = fmaxf(mx0, __shfl_xor_sync(0xffffffffu, mx0, 1));
        mx0 = fmaxf(mx0, __shfl_xor_sync(0xffffffffu, mx0, 2));
        mx1 = fmaxf(mx1, __shfl_xor_sync(0xffffffffu, mx1, 1));
        mx1 = fmaxf(mx1, __shfl_xor_sync(0xffffffffu, mx1, 2));

        const float m0n = fmaxf(m0, mx0);
        const float m1n = fmaxf(m1, mx1);
        const float c0  = __expf(m0 - m0n);
        const float c1  = __expf(m1 - m1n);

        float sum0 = 0.0f, sum1 = 0.0f;
#pragma unroll
        for (int t = 0; t < 8; t++) {
            s[t][0] = __expf(s[t][0] - m0n);
            s[t][1] = __expf(s[t][1] - m0n);
            s[t][2] = __expf(s[t][2] - m1n);
            s[t][3] = __expf(s[t][3] - m1n);
            sum0 += s[t][0] + s[t][1];
            sum1 += s[t][2] + s[t][3];
        }
        sum0 += __shfl_xor_sync(0xffffffffu, sum0, 1);
        sum0 += __shfl_xor_sync(0xffffffffu, sum0, 2);
        sum1 += __shfl_xor_sync(0xffffffffu, sum1, 1);
        sum1 += __shfl_xor_sync(0xffffffffu, sum1, 2);

        l0 = l0 * c0 + sum0;
        l1 = l1 * c1 + sum1;
        m0 = m0n;
        m1 = m1n;

        // ---- rescale O (registers) ----
#pragma unroll
        for (int t = 0; t < 8; t++) {
            o[t][0] *= c0; o[t][1] *= c0;
            o[t][2] *= c1; o[t][3] *= c1;
        }

        // ---- O += P V.  P A-fragments built from s[j] via quad shuffles:
        // accumulator lane layout (row g, cols 2q,2q+1) -> A layout (cols q, q+4).
#pragma unroll
        for (int j = 0; j < 8; j++) {              // k over kv rows (chunk j)
            float u0 = __shfl_sync(0xffffffffu, s[j][0], srcA);
            float u1 = __shfl_sync(0xffffffffu, s[j][1], srcA);
            float v0 = __shfl_sync(0xffffffffu, s[j][0], srcB);
            float v1 = __shfl_sync(0xffffffffu, s[j][1], srcB);
            float w0 = __shfl_sync(0xffffffffu, s[j][2], srcA);
            float w1 = __shfl_sync(0xffffffffu, s[j][3], srcA);
            float x0 = __shfl_sync(0xffffffffu, s[j][2], srcB);
            float x1 = __shfl_sync(0xffffffffu, s[j][3], srcB);
            unsigned a[4];
            a[0] = f2tf(odd ? u1 : u0);            // P[g][8j+q]
            a[1] = f2tf(odd ? w1 : w0);            // P[g+8][8j+q]
            a[2] = f2tf(odd ? v1 : v0);            // P[g][8j+q+4]
            a[3] = f2tf(odd ? x1 : x0);            // P[g+8][8j+q+4]
#pragma unroll
            for (int t = 0; t < 8; t++) {          // n over dh
                unsigned bf[2];
                bf[0] = Vu[(j * 8 + q) * VSTR + t * 8 + g];
                bf[1] = Vu[(j * 8 + q + 4) * VSTR + t * 8 + g];
                mma_tf32_16n8k8(o[t], a, bf);
            }
        }
    }

    // ---- normalize & write concat layout [b, l, h*64 + d] ----
    const float inv0 = 1.0f / l0;
    const float inv1 = 1.0f / l1;
    float* orow0 = Og + ((size_t)b * cfg::Ls + q0 + wrow + g) * cfg::Din + h * cfg::Dh;
    float* orow1 = orow0 + 8 * (size_t)cfg::Din;
#pragma unroll
    for (int t = 0; t < 8; t++) {
        float2 w0 = { o[t][0] * inv0, o[t][1] * inv0 };
        float2 w1 = { o[t][2] * inv1, o[t][3] * inv1 };
        *(float2*)&orow0[t * 8 + 2 * q] = w0;
        *(float2*)&orow1[t * 8 + 2 * q] = w1;
    }
}

// ---------------------------------------------------------------------------
// Fused residual-add + LayerNorm over last dim (512). One block per row.
// ---------------------------------------------------------------------------
__global__ __launch_bounds__(128) void ln_add_kernel(
    const float* __restrict__ x, const float* __restrict__ y, float* __restrict__ out)
{
    const int row = blockIdx.x;
    const float* px = x + (size_t)row * cfg::Din;
    const float* py = y + (size_t)row * cfg::Din;

    float v[4];
    float s = 0.0f, sq = 0.0f;
#pragma unroll
    for (int i = 0; i < 4; i++) {
        int c = threadIdx.x + i * 128;
        v[i] = px[c] + py[c];
        s  += v[i];
        sq += v[i] * v[i];
    }
#pragma unroll
    for (int o = 16; o > 0; o >>= 1) {
        s  += __shfl_xor_sync(0xffffffffu, s, o);
        sq += __shfl_xor_sync(0xffffffffu, sq, o);
    }
    __shared__ float ws[4], wq[4];
    __shared__ float mean_s, inv_s;
    const int warp = threadIdx.x >> 5, lane = threadIdx.x & 31;
    if (lane == 0) { ws[warp] = s; wq[warp] = sq; }
    __syncthreads();
    if (threadIdx.x == 0) {
        float S = ws[0] + ws[1] + ws[2] + ws[3];
        float Q = wq[0] + wq[1] + wq[2] + wq[3];
        float mean = S * (1.0f / cfg::Din);
        float var  = Q * (1.0f / cfg::Din) - mean * mean;
        mean_s = mean;
        inv_s  = rsqrtf(var + 1e-5f);
    }
    __syncthreads();
    float* po = out + (size_t)row * cfg::Din;
#pragma unroll
    for (int i = 0; i < 4; i++) {
        int c = threadIdx.x + i * 128;
        po[c] = (v[i] - mean_s) * inv_s;
    }
}

// ---------------------------------------------------------------------------
// kernel_launch
// ---------------------------------------------------------------------------
extern "C" void kernel_launch(void* const* d_in, const int* in_sizes, int n_in,
                              void* d_out, int out_size)
{
    const float* query = (const float*)d_in[0];
    const float* key   = (const float*)d_in[1];
    const float* value = (const float*)d_in[2];
    const float* mask  = (const float*)d_in[3];
    const float* WQ    = (const float*)d_in[4];
    const float* WK    = (const float*)d_in[5];
    const float* WV    = (const float*)d_in[6];
    const float* WO    = (const float*)d_in[7];
    const float* W1    = (const float*)d_in[8];
    const float* W2    = (const float*)d_in[9];
    float* out = (float*)d_out;

    float *Qd, *Kd, *Vd, *attn, *proj, *h1, *mid, *ff;
    cudaGetSymbolAddress((void**)&Qd,   g_Q);
    cudaGetSymbolAddress((void**)&Kd,   g_K);
    cudaGetSymbolAddress((void**)&Vd,   g_V);
    cudaGetSymbolAddress((void**)&attn, g_attn);
    cudaGetSymbolAddress((void**)&proj, g_proj);
    cudaGetSymbolAddress((void**)&h1,   g_h1);
    cudaGetSymbolAddress((void**)&mid,  g_mid);
    cudaGetSymbolAddress((void**)&ff,   g_ff);

    cudaFuncSetAttribute(flash2_kernel, cudaFuncAttributeMaxDynamicSharedMemorySize,
                         (int)FLASH2_SMEM);

    const dim3 gProj(cfg::Din / BN, cfg::Mtok / BM);        // (4, 64)
    const dim3 gQkv (cfg::Din / BN, cfg::Mtok / BM, 3);     // (4, 64, 3)
    const dim3 gFfn1(cfg::Dmid / BN, cfg::Mtok / BM);       // (16, 64)

    // Fused QKV projections (head-split epilogue)
    gemm_qkv<<<gQkv, 256>>>(query, key, value, WQ, WK, WV, Qd, Kd, Vd);

    // Flash attention
    dim3 gFlash(cfg::Ls / FQ2, cfg::Hh, cfg::Bb);           // (16, 8, 4)
    flash2_kernel<<<gFlash, 256, FLASH2_SMEM>>>(Qd, Kd, Vd, mask, attn);

    // Output projection + residual LN
    gemm_tf32<0><<<gProj, 256>>>(attn, WO, proj, cfg::Mtok, cfg::Din, cfg::Din);
    ln_add_kernel<<<cfg::Mtok, 128>>>(query, proj, h1);

    // FFN
    gemm_tf32<1><<<gFfn1, 256>>>(h1,  W1, mid, cfg::Mtok, cfg::Dmid, cfg::Din);
    gemm_tf32<0><<<gProj, 256>>>(mid, W2, ff,  cfg::Mtok, cfg::Din, cfg::Dmid);
    ln_add_kernel<<<cfg::Mtok, 128>>>(h1, ff, out);

    (void)in_sizes; (void)n_in; (void)out_size;
}

// round 10
// speedup vs baseline: 3.1700x; 1.1113x over previous
#include <cuda_runtime.h>
#include <mma.h>
#include <math_constants.h>
#include <cstdint>
#include <cstddef>

using namespace nvcuda;

// ---------------------------------------------------------------------------
// Problem constants
// ---------------------------------------------------------------------------
namespace cfg {
constexpr int Bb   = 4;
constexpr int Ls   = 2048;
constexpr int Din  = 512;
constexpr int Hh   = 8;
constexpr int Dh   = 64;
constexpr int Dmid = 2048;
constexpr int Mtok = Bb * Ls;   // 8192 tokens
}

// ---------------------------------------------------------------------------
// Scratch (static device globals — no allocations anywhere)
// ---------------------------------------------------------------------------
__device__ float g_Q[cfg::Bb * cfg::Hh * cfg::Ls * cfg::Dh];   // [b,h,l,d] tf32 bits
__device__ float g_K[cfg::Bb * cfg::Hh * cfg::Ls * cfg::Dh];   // tf32 bits
__device__ float g_V[cfg::Bb * cfg::Hh * cfg::Ls * cfg::Dh];   // tf32 bits
__device__ float g_attn[cfg::Mtok * cfg::Din];                 // tf32 bits
__device__ float g_proj[cfg::Mtok * cfg::Din];                 // fp32
__device__ float g_h1[cfg::Mtok * cfg::Din];                   // fp32 (residual)
__device__ float g_h1t[cfg::Mtok * cfg::Din];                  // tf32 bits (FFN1 A)
__device__ float g_mid[cfg::Mtok * cfg::Dmid];                 // tf32 bits
__device__ float g_ff[cfg::Mtok * cfg::Din];                   // fp32

// Pre-truncated tf32 copies of inputs + weights
__device__ float g_qt[cfg::Mtok * cfg::Din];
__device__ float g_kt[cfg::Mtok * cfg::Din];
__device__ float g_vt[cfg::Mtok * cfg::Din];
__device__ float g_WQt[cfg::Din * cfg::Din];
__device__ float g_WKt[cfg::Din * cfg::Din];
__device__ float g_WVt[cfg::Din * cfg::Din];
__device__ float g_WOt[cfg::Din * cfg::Din];
__device__ float g_W1t[cfg::Din * cfg::Dmid];
__device__ float g_W2t[cfg::Dmid * cfg::Din];

// ---------------------------------------------------------------------------
// cp.async helpers
// ---------------------------------------------------------------------------
__device__ __forceinline__ void cpa16(void* smem, const void* gmem) {
    unsigned sa = (unsigned)__cvta_generic_to_shared(smem);
    asm volatile("cp.async.cg.shared.global [%0], [%1], 16;" :: "r"(sa), "l"(gmem));
}
__device__ __forceinline__ void cpa_commit() {
    asm volatile("cp.async.commit_group;");
}
template <int N>
__device__ __forceinline__ void cpa_wait() {
    asm volatile("cp.async.wait_group %0;" :: "n"(N));
}

__device__ __forceinline__ unsigned f2tf(float f) {
    unsigned u;
    asm("cvt.rna.tf32.f32 %0, %1;" : "=r"(u) : "f"(f));
    return u;
}
__device__ __forceinline__ float f2tf_f(float f) { return __uint_as_float(f2tf(f)); }

// mma.m16n8k8 tf32: A 4 regs, B 2 regs, C/D 4 floats (in-place accumulate)
__device__ __forceinline__ void mma_tf32_16n8k8(float d[4], const unsigned a[4],
                                                const unsigned b[2]) {
    asm volatile(
        "mma.sync.aligned.m16n8k8.row.col.f32.tf32.tf32.f32 "
        "{%0,%1,%2,%3}, {%4,%5,%6,%7}, {%8,%9}, {%0,%1,%2,%3};"
        : "+f"(d[0]), "+f"(d[1]), "+f"(d[2]), "+f"(d[3])
        : "r"(a[0]), "r"(a[1]), "r"(a[2]), "r"(a[3]), "r"(b[0]), "r"(b[1]));
}

// ---------------------------------------------------------------------------
// One-pass fp32 -> tf32-bits conversion (rna), vectorized float4.
// ---------------------------------------------------------------------------
__global__ __launch_bounds__(256) void cvt_tf32_kernel(
    const float* __restrict__ in, float* __restrict__ outp, int n)
{
    int i = (blockIdx.x * 256 + threadIdx.x) * 4;
    const int stride = gridDim.x * 256 * 4;
    for (; i < n; i += stride) {
        float4 v = *(const float4*)(in + i);
        v.x = f2tf_f(v.x); v.y = f2tf_f(v.y);
        v.z = f2tf_f(v.z); v.w = f2tf_f(v.w);
        *(float4*)(outp + i) = v;
    }
}

// ---------------------------------------------------------------------------
// tf32 GEMM, operands PRE-TRUNCATED to tf32 bits (no cvt in mainloop).
// C[M,N] = A[M,K] * B[K,N], fp32 accum. Block tile 128x128x16, 3-stage
// cp.async pipeline, ONE __syncthreads per k-iter. 256 threads (8 warps),
// warp tile 64x32.
// Epilogues: 0 = plain fp32, 2 = head-split [b,h,l,64] + tf32 cvt,
//            3 = relu + tf32 cvt.
// ---------------------------------------------------------------------------
constexpr int BM = 128, BN = 128, BK = 16;
constexpr int ALD = BK + 4;        // 20
constexpr int BLD = BN + 4;        // 132
constexpr int AS_F = BM * ALD;     // 2560 floats / stage
constexpr int BS_F = BK * BLD;     // 2112 floats / stage
constexpr int GST  = 3;
constexpr size_t GEMM_SMEM = (size_t)GST * (AS_F + BS_F) * sizeof(float);  // 56,064 B

template <int EPI>
__device__ __forceinline__ void gemm_dev(
    const float* __restrict__ A, const float* __restrict__ Bw,
    float* __restrict__ C, int M, int N, int K)
{
    extern __shared__ float gsm[];
    float* As = gsm;
    float* Bs = gsm + GST * AS_F;

    const int tid  = threadIdx.x;
    const int bm   = blockIdx.y * BM;
    const int bn   = blockIdx.x * BN;
    const int warp = tid >> 5;
    const int lane = tid & 31;
    const int wr   = warp >> 2;   // 0..1
    const int wc   = warp & 3;    // 0..3

    wmma::fragment<wmma::accumulator, 16, 16, 8, float> acc[4][2];
#pragma unroll
    for (int mi = 0; mi < 4; mi++)
#pragma unroll
        for (int ni = 0; ni < 2; ni++) wmma::fill_fragment(acc[mi][ni], 0.0f);

    auto load_tiles = [&](int buf, int kt) {
        const int k0 = kt * BK;
        float* Ab = As + buf * AS_F;
        float* Bb = Bs + buf * BS_F;
#pragma unroll
        for (int i = 0; i < 2; i++) {
            int lin = tid + i * 256;          // 0..511
            int r   = lin >> 2;
            int c4  = (lin & 3) * 4;
            cpa16(Ab + r * ALD + c4, A + (size_t)(bm + r) * K + k0 + c4);
        }
#pragma unroll
        for (int i = 0; i < 2; i++) {
            int lin = tid + i * 256;
            int r   = lin >> 5;
            int c4  = (lin & 31) * 4;
            cpa16(Bb + r * BLD + c4, Bw + (size_t)(k0 + r) * N + bn + c4);
        }
        cpa_commit();
    };

    const int nkt = K / BK;       // >= 32 for all our shapes
    load_tiles(0, 0);
    load_tiles(1, 1);

    for (int kt = 0; kt < nkt; kt++) {
        if (kt + 1 < nkt) cpa_wait<1>(); else cpa_wait<0>();
        __syncthreads();
        // Prefetch stage kt+2 (writes a stage no warp reads this iter; all
        // warps passed the barrier, so reads of that stage from iter kt-1 done).
        if (kt + 2 < nkt) load_tiles((kt + 2) % GST, kt + 2);

        const int buf = kt % GST;
        const float* Ab = As + buf * AS_F;
        const float* Bb = Bs + buf * BS_F;
#pragma unroll
        for (int ks = 0; ks < 2; ks++) {
            wmma::fragment<wmma::matrix_a, 16, 16, 8, wmma::precision::tf32, wmma::row_major> af[4];
            wmma::fragment<wmma::matrix_b, 16, 16, 8, wmma::precision::tf32, wmma::row_major> bf[2];
#pragma unroll
            for (int mi = 0; mi < 4; mi++)
                wmma::load_matrix_sync(af[mi], Ab + (wr * 64 + mi * 16) * ALD + ks * 8, ALD);
#pragma unroll
            for (int ni = 0; ni < 2; ni++)
                wmma::load_matrix_sync(bf[ni], Bb + (ks * 8) * BLD + wc * 32 + ni * 16, BLD);
#pragma unroll
            for (int mi = 0; mi < 4; mi++)
#pragma unroll
                for (int ni = 0; ni < 2; ni++)
                    wmma::mma_sync(acc[mi][ni], af[mi], bf[ni], acc[mi][ni]);
        }
    }
    __syncthreads();   // protect smem reuse by epilogue staging

    float* stg = gsm + warp * (16 * 20);
#pragma unroll
    for (int mi = 0; mi < 4; mi++) {
#pragma unroll
        for (int ni = 0; ni < 2; ni++) {
            wmma::store_matrix_sync(stg, acc[mi][ni], 20, wmma::mem_row_major);
            __syncwarp();
#pragma unroll
            for (int e = 0; e < 8; e++) {
                int idx = lane + e * 32;
                int r = idx >> 4, c = idx & 15;
                int gr = bm + wr * 64 + mi * 16 + r;
                int gc = bn + wc * 32 + ni * 16 + c;
                float v = stg[r * 20 + c];
                if (EPI == 3) v = fmaxf(v, 0.0f);
                if (EPI == 2) {
                    int b = gr >> 11;              // Ls = 2048
                    int l = gr & (cfg::Ls - 1);
                    int h = gc >> 6;               // Dh = 64
                    int d = gc & 63;
                    C[(((size_t)(b * cfg::Hh + h) * cfg::Ls + l) << 6) + d] = f2tf_f(v);
                } else if (EPI == 3) {
                    C[(size_t)gr * N + gc] = f2tf_f(v);
                } else {
                    C[(size_t)gr * N + gc] = v;
                }
            }
            __syncwarp();
        }
    }
}

template <int EPI>
__global__ __launch_bounds__(256, 2) void gemm_tf32(
    const float* __restrict__ A, const float* __restrict__ Bw,
    float* __restrict__ C, int M, int N, int K)
{
    gemm_dev<EPI>(A, Bw, C, M, N, K);
}

// Fused QKV projection: blockIdx.z selects (input, weight, output) triple.
__global__ __launch_bounds__(256, 2) void gemm_qkv(
    const float* __restrict__ q, const float* __restrict__ k,
    const float* __restrict__ v,
    const float* __restrict__ WQ, const float* __restrict__ WK,
    const float* __restrict__ WV,
    float* __restrict__ Qd, float* __restrict__ Kd, float* __restrict__ Vd)
{
    const int z = blockIdx.z;
    const float* A = (z == 0) ? q : (z == 1) ? k : v;
    const float* W = (z == 0) ? WQ : (z == 1) ? WK : WV;
    float* C       = (z == 0) ? Qd : (z == 1) ? Kd : Vd;
    gemm_dev<2>(A, W, C, cfg::Mtok, cfg::Din, cfg::Din);
}

// ---------------------------------------------------------------------------
// Flash attention: raw mma.m16n8k8.tf32, S and O register-resident.
// Q/K/V arrive PRE-TRUNCATED to tf32 bits (QKV GEMM epilogue), so the
// mainloop has no conversion pass: 1 barrier per kv-tile.
// Block = (b, h, 128 q-rows); 256 threads (8 warps), warp owns 16 rows.
// ---------------------------------------------------------------------------
constexpr int FQ2  = 128;
constexpr int QSTR = 68;   // 68 % 32 == 4 -> conflict-free Q/K frag loads
constexpr int KSTR = 68;
constexpr int VSTR = 72;   // 72 % 32 == 8 -> conflict-free V frag loads

constexpr int SM_Q = 0;                        // 128*68
constexpr int SM_K = SM_Q + FQ2 * QSTR;        // 2 * 64*68
constexpr int SM_V = SM_K + 2 * 64 * KSTR;     // 2 * 64*72
constexpr int FLASH2_FLOATS = SM_V + 2 * 64 * VSTR;           // 26624
constexpr size_t FLASH2_SMEM = (size_t)FLASH2_FLOATS * sizeof(float);  // 106,496 B

__global__ __launch_bounds__(256, 2) void flash2_kernel(
    const float* __restrict__ Qg, const float* __restrict__ Kg,
    const float* __restrict__ Vg, const float* __restrict__ maskg,
    float* __restrict__ Og)
{
    extern __shared__ float sm[];
    float* Qs = sm + SM_Q;
    float* Ks = sm + SM_K;
    float* Vs = sm + SM_V;

    const int tid  = threadIdx.x;
    const int warp = tid >> 5;
    const int lane = tid & 31;
    const int g    = lane >> 2;     // fragment row group (0..7)
    const int q    = lane & 3;      // thread-in-group (0..3)
    const int b    = blockIdx.z;
    const int h    = blockIdx.y;
    const int q0   = blockIdx.x * FQ2;
    const int wrow = warp * 16;

    const size_t bh = (size_t)(b * cfg::Hh + h) * cfg::Ls;
    const float* Qbase = Qg + (bh + q0) * cfg::Dh;

    // Q: 128 rows x 16 float4 via cp.async
#pragma unroll
    for (int i = 0; i < 8; i++) {
        int lin = tid + i * 256;
        int r = lin >> 4, c4 = (lin & 15) * 4;
        cpa16(&Qs[r * QSTR + c4], Qbase + r * cfg::Dh + c4);
    }

    auto loadKV = [&](int buf, int kt) {
        const float* Kb = Kg + (bh + kt * 64) * cfg::Dh;
        const float* Vb = Vg + (bh + kt * 64) * cfg::Dh;
#pragma unroll
        for (int i = 0; i < 4; i++) {
            int lin = tid + i * 256;
            int r = lin >> 4, c4 = (lin & 15) * 4;
            cpa16(&Ks[buf * 64 * KSTR + r * KSTR + c4], Kb + r * cfg::Dh + c4);
            cpa16(&Vs[buf * 64 * VSTR + r * VSTR + c4], Vb + r * cfg::Dh + c4);
        }
    };
    loadKV(0, 0);
    cpa_commit();

    // Register state: rows (wrow+g) and (wrow+g+8)
    float m0 = -CUDART_INF_F, m1 = -CUDART_INF_F;
    float l0 = 0.0f, l1 = 0.0f;
    float o[8][4];
#pragma unroll
    for (int t = 0; t < 8; t++)
#pragma unroll
        for (int e = 0; e < 4; e++) o[t][e] = 0.0f;

    const float* mrow0 = maskg + ((size_t)b * cfg::Ls + q0 + wrow + g) * cfg::Ls;
    const float* mrow1 = mrow0 + 8 * (size_t)cfg::Ls;

    const unsigned* Qu = (const unsigned*)Qs;
    const int srcA = (lane & 28) | (q >> 1);   // owner of P col q within quad
    const int srcB = srcA + 2;                 // owner of P col q+4
    const bool odd = (q & 1) != 0;

    for (int kt = 0; kt < cfg::Ls / 64; kt++) {
        const int cur = kt & 1;
        cpa_wait<0>();
        __syncthreads();
        if (kt + 1 < cfg::Ls / 64) { loadKV(cur ^ 1, kt + 1); cpa_commit(); }

        const unsigned* Ku = (const unsigned*)(Ks + cur * 64 * KSTR);
        const unsigned* Vu = (const unsigned*)(Vs + cur * 64 * VSTR);

        // ---- S = Q K^T (registers) ----
        float s[8][4];
#pragma unroll
        for (int t = 0; t < 8; t++)
#pragma unroll
            for (int e = 0; e < 4; e++) s[t][e] = 0.0f;

#pragma unroll
        for (int j = 0; j < 8; j++) {              // k over dh
            unsigned a[4];
            a[0] = Qu[(wrow + g) * QSTR + j * 8 + q];
            a[1] = Qu[(wrow + g + 8) * QSTR + j * 8 + q];
            a[2] = Qu[(wrow + g) * QSTR + j * 8 + q + 4];
            a[3] = Qu[(wrow + g + 8) * QSTR + j * 8 + q + 4];
#pragma unroll
            for (int t = 0; t < 8; t++) {          // n over kv rows
                unsigned bf[2];
                bf[0] = Ku[(t * 8 + g) * KSTR + j * 8 + q];
                bf[1] = Ku[(t * 8 + g) * KSTR + j * 8 + q + 4];
                mma_tf32_16n8k8(s[t], a, bf);
            }
        }

        // ---- scale + mask ----
        const int kcol = kt * 64;
#pragma unroll
        for (int t = 0; t < 8; t++) {
            float2 mk0 = *(const float2*)(mrow0 + kcol + t * 8 + 2 * q);
            float2 mk1 = *(const float2*)(mrow1 + kcol + t * 8 + 2 * q);
            s[t][0] = s[t][0] * 0.125f + mk0.x;
            s[t][1] = s[t][1] * 0.125f + mk0.y;
            s[t][2] = s[t][2] * 0.125f + mk1.x;
            s[t][3] = s[t][3] * 0.125f + mk1.y;
        }

        // ---- online softmax (register + 2 shfl per row) ----
        float mx0 = -CUDART_INF_F, mx1 = -CUDART_INF_F;
#pragma unroll
        for (int t = 0; t < 8; t++) {
            mx0 = fmaxf(mx0, fmaxf(s[t][0], s[t][1]));
            mx1 = fmaxf(mx1, fmaxf(s[t][2], s[t][3]));
        }
        mx0 = fmaxf(mx0, __shfl_xor_sync(0xffffffffu, mx0, 1));
        mx0 = fmaxf(mx0, __shfl_xor_sync(0xffffffffu, mx0, 2));
        mx1 = fmaxf(mx1, __shfl_xor_sync(0xffffffffu, mx1, 1));
        mx1 = fmaxf(mx1, __shfl_xor_sync(0xffffffffu, mx1, 2));

        const float m0n = fmaxf(m0, mx0);
        const float m1n = fmaxf(m1, mx1);
        const float c0  = __expf(m0 - m0n);
        const float c1  = __expf(m1 - m1n);

        float sum0 = 0.0f, sum1 = 0.0f;
#pragma unroll
        for (int t = 0; t < 8; t++) {
            s[t][0] = __expf(s[t][0] - m0n);
            s[t][1] = __expf(s[t][1] - m0n);
            s[t][2] = __expf(s[t][2] - m1n);
            s[t][3] = __expf(s[t][3] - m1n);
            sum0 += s[t][0] + s[t][1];
            sum1 += s[t][2] + s[t][3];
        }
        sum0 += __shfl_xor_sync(0xffffffffu, sum0, 1);
        sum0 += __shfl_xor_sync(0xffffffffu, sum0, 2);
        sum1 += __shfl_xor_sync(0xffffffffu, sum1, 1);
        sum1 += __shfl_xor_sync(0xffffffffu, sum1, 2);

        l0 = l0 * c0 + sum0;
        l1 = l1 * c1 + sum1;
        m0 = m0n;
        m1 = m1n;

        // ---- rescale O (registers) ----
#pragma unroll
        for (int t = 0; t < 8; t++) {
            o[t][0] *= c0; o[t][1] *= c0;
            o[t][2] *= c1; o[t][3] *= c1;
        }

        // ---- O += P V.  P A-fragments built from s[j] via quad shuffles ----
#pragma unroll
        for (int j = 0; j < 8; j++) {              // k over kv rows (chunk j)
            float u0 = __shfl_sync(0xffffffffu, s[j][0], srcA);
            float u1 = __shfl_sync(0xffffffffu, s[j][1], srcA);
            float v0 = __shfl_sync(0xffffffffu, s[j][0], srcB);
            float v1 = __shfl_sync(0xffffffffu, s[j][1], srcB);
            float w0 = __shfl_sync(0xffffffffu, s[j][2], srcA);
            float w1 = __shfl_sync(0xffffffffu, s[j][3], srcA);
            float x0 = __shfl_sync(0xffffffffu, s[j][2], srcB);
            float x1 = __shfl_sync(0xffffffffu, s[j][3], srcB);
            unsigned a[4];
            a[0] = f2tf(odd ? u1 : u0);            // P[g][8j+q]
            a[1] = f2tf(odd ? w1 : w0);            // P[g+8][8j+q]
            a[2] = f2tf(odd ? v1 : v0);            // P[g][8j+q+4]
            a[3] = f2tf(odd ? x1 : x0);            // P[g+8][8j+q+4]
#pragma unroll
            for (int t = 0; t < 8; t++) {          // n over dh
                unsigned bf[2];
                bf[0] = Vu[(j * 8 + q) * VSTR + t * 8 + g];
                bf[1] = Vu[(j * 8 + q + 4) * VSTR + t * 8 + g];
                mma_tf32_16n8k8(o[t], a, bf);
            }
        }
    }

    // ---- normalize, tf32-truncate (feeds WO GEMM) & write concat layout ----
    const float inv0 = 1.0f / l0;
    const float inv1 = 1.0f / l1;
    float* orow0 = Og + ((size_t)b * cfg::Ls + q0 + wrow + g) * cfg::Din + h * cfg::Dh;
    float* orow1 = orow0 + 8 * (size_t)cfg::Din;
#pragma unroll
    for (int t = 0; t < 8; t++) {
        float2 w0 = { f2tf_f(o[t][0] * inv0), f2tf_f(o[t][1] * inv0) };
        float2 w1 = { f2tf_f(o[t][2] * inv1), f2tf_f(o[t][3] * inv1) };
        *(float2*)&orow0[t * 8 + 2 * q] = w0;
        *(float2*)&orow1[t * 8 + 2 * q] = w1;
    }
}

// ---------------------------------------------------------------------------
// Fused residual-add + LayerNorm over last dim (512). One block per row.
// Optionally also writes a tf32-truncated copy (A operand for next GEMM).
// ---------------------------------------------------------------------------
template <bool T32>
__global__ __launch_bounds__(128) void ln_add_kernel(
    const float* __restrict__ x, const float* __restrict__ y,
    float* __restrict__ out, float* __restrict__ out_t)
{
    const int row = blockIdx.x;
    const float* px = x + (size_t)row * cfg::Din;
    const float* py = y + (size_t)row * cfg::Din;

    float v[4];
    float s = 0.0f, sq = 0.0f;
#pragma unroll
    for (int i = 0; i < 4; i++) {
        int c = threadIdx.x + i * 128;
        v[i] = px[c] + py[c];
        s  += v[i];
        sq += v[i] * v[i];
    }
#pragma unroll
    for (int o = 16; o > 0; o >>= 1) {
        s  += __shfl_xor_sync(0xffffffffu, s, o);
        sq += __shfl_xor_sync(0xffffffffu, sq, o);
    }
    __shared__ float ws[4], wq[4];
    __shared__ float mean_s, inv_s;
    const int warp = threadIdx.x >> 5, lane = threadIdx.x & 31;
    if (lane == 0) { ws[warp] = s; wq[warp] = sq; }
    __syncthreads();
    if (threadIdx.x == 0) {
        float S = ws[0] + ws[1] + ws[2] + ws[3];
        float Q = wq[0] + wq[1] + wq[2] + wq[3];
        float mean = S * (1.0f / cfg::Din);
        float var  = Q * (1.0f / cfg::Din) - mean * mean;
        mean_s = mean;
        inv_s  = rsqrtf(var + 1e-5f);
    }
    __syncthreads();
    float* po = out + (size_t)row * cfg::Din;
    float* pt = out_t + (size_t)row * cfg::Din;
#pragma unroll
    for (int i = 0; i < 4; i++) {
        int c = threadIdx.x + i * 128;
        float r = (v[i] - mean_s) * inv_s;
        po[c] = r;
        if (T32) pt[c] = f2tf_f(r);
    }
}

// ---------------------------------------------------------------------------
// kernel_launch
// ---------------------------------------------------------------------------
extern "C" void kernel_launch(void* const* d_in, const int* in_sizes, int n_in,
                              void* d_out, int out_size)
{
    const float* query = (const float*)d_in[0];
    const float* key   = (const float*)d_in[1];
    const float* value = (const float*)d_in[2];
    const float* mask  = (const float*)d_in[3];
    const float* WQ    = (const float*)d_in[4];
    const float* WK    = (const float*)d_in[5];
    const float* WV    = (const float*)d_in[6];
    const float* WO    = (const float*)d_in[7];
    const float* W1    = (const float*)d_in[8];
    const float* W2    = (const float*)d_in[9];
    float* out = (float*)d_out;

    float *Qd, *Kd, *Vd, *attn, *proj, *h1, *h1t, *mid, *ff;
    float *qt, *kt, *vt, *WQt, *WKt, *WVt, *WOt, *W1t, *W2t;
    cudaGetSymbolAddress((void**)&Qd,   g_Q);
    cudaGetSymbolAddress((void**)&Kd,   g_K);
    cudaGetSymbolAddress((void**)&Vd,   g_V);
    cudaGetSymbolAddress((void**)&attn, g_attn);
    cudaGetSymbolAddress((void**)&proj, g_proj);
    cudaGetSymbolAddress((void**)&h1,   g_h1);
    cudaGetSymbolAddress((void**)&h1t,  g_h1t);
    cudaGetSymbolAddress((void**)&mid,  g_mid);
    cudaGetSymbolAddress((void**)&ff,   g_ff);
    cudaGetSymbolAddress((void**)&qt,   g_qt);
    cudaGetSymbolAddress((void**)&kt,   g_kt);
    cudaGetSymbolAddress((void**)&vt,   g_vt);
    cudaGetSymbolAddress((void**)&WQt,  g_WQt);
    cudaGetSymbolAddress((void**)&WKt,  g_WKt);
    cudaGetSymbolAddress((void**)&WVt,  g_WVt);
    cudaGetSymbolAddress((void**)&WOt,  g_WOt);
    cudaGetSymbolAddress((void**)&W1t,  g_W1t);
    cudaGetSymbolAddress((void**)&W2t,  g_W2t);

    cudaFuncSetAttribute(flash2_kernel, cudaFuncAttributeMaxDynamicSharedMemorySize,
                         (int)FLASH2_SMEM);
    cudaFuncSetAttribute(gemm_tf32<0>, cudaFuncAttributeMaxDynamicSharedMemorySize,
                         (int)GEMM_SMEM);
    cudaFuncSetAttribute(gemm_tf32<3>, cudaFuncAttributeMaxDynamicSharedMemorySize,
                         (int)GEMM_SMEM);
    cudaFuncSetAttribute(gemm_qkv, cudaFuncAttributeMaxDynamicSharedMemorySize,
                         (int)GEMM_SMEM);

    // -- one-pass tf32 truncation of raw inputs + weights --
    auto cvt = [&](const float* src, float* dst, int n) {
        cvt_tf32_kernel<<<n / 1024, 256>>>(src, dst, n);
    };
    const int nIn = cfg::Mtok * cfg::Din;      // 4,194,304
    const int nWs = cfg::Din * cfg::Din;       // 262,144
    const int nWf = cfg::Din * cfg::Dmid;      // 1,048,576
    cvt(query, qt, nIn); cvt(key, kt, nIn); cvt(value, vt, nIn);
    cvt(WQ, WQt, nWs); cvt(WK, WKt, nWs); cvt(WV, WVt, nWs);
    cvt(WO, WOt, nWs); cvt(W1, W1t, nWf); cvt(W2, W2t, nWf);

    const dim3 gProj(cfg::Din / BN, cfg::Mtok / BM);        // (4, 64)
    const dim3 gQkv (cfg::Din / BN, cfg::Mtok / BM, 3);     // (4, 64, 3)
    const dim3 gFfn1(cfg::Dmid / BN, cfg::Mtok / BM);       // (16, 64)

    // Fused QKV projections (head-split + tf32 epilogue)
    gemm_qkv<<<gQkv, 256, GEMM_SMEM>>>(qt, kt, vt, WQt, WKt, WVt, Qd, Kd, Vd);

    // Flash attention (consumes tf32 Q/K/V, emits tf32 attn)
    dim3 gFlash(cfg::Ls / FQ2, cfg::Hh, cfg::Bb);           // (16, 8, 4)
    flash2_kernel<<<gFlash, 256, FLASH2_SMEM>>>(Qd, Kd, Vd, mask, attn);

    // Output projection + residual LN (fp32 out + tf32 copy for FFN1)
    gemm_tf32<0><<<gProj, 256, GEMM_SMEM>>>(attn, WOt, proj, cfg::Mtok, cfg::Din, cfg::Din);
    ln_add_kernel<true><<<cfg::Mtok, 128>>>(query, proj, h1, h1t);

    // FFN (FFN1: relu + tf32 epilogue; FFN2: fp32)
    gemm_tf32<3><<<gFfn1, 256, GEMM_SMEM>>>(h1t, W1t, mid, cfg::Mtok, cfg::Dmid, cfg::Din);
    gemm_tf32<0><<<gProj, 256, GEMM_SMEM>>>(mid, W2t, ff, cfg::Mtok, cfg::Din, cfg::Dmid);
    ln_add_kernel<false><<<cfg::Mtok, 128>>>(h1, ff, out, out);

    (void)in_sizes; (void)n_in; (void)out_size;
}

// round 11
// speedup vs baseline: 3.2473x; 1.0244x over previous
#include <cuda_runtime.h>
#include <mma.h>
#include <math_constants.h>
#include <cstdint>
#include <cstddef>

using namespace nvcuda;

// ---------------------------------------------------------------------------
// Problem constants
// ---------------------------------------------------------------------------
namespace cfg {
constexpr int Bb   = 4;
constexpr int Ls   = 2048;
constexpr int Din  = 512;
constexpr int Hh   = 8;
constexpr int Dh   = 64;
constexpr int Dmid = 2048;
constexpr int Mtok = Bb * Ls;   // 8192 tokens
}

// ---------------------------------------------------------------------------
// Scratch (static device globals — no allocations anywhere)
// ---------------------------------------------------------------------------
__device__ float g_Q[cfg::Bb * cfg::Hh * cfg::Ls * cfg::Dh];   // [b,h,l,d] tf32 bits
__device__ float g_K[cfg::Bb * cfg::Hh * cfg::Ls * cfg::Dh];   // tf32 bits
__device__ float g_V[cfg::Bb * cfg::Hh * cfg::Ls * cfg::Dh];   // tf32 bits
__device__ float g_attn[cfg::Mtok * cfg::Din];                 // tf32 bits
__device__ float g_proj[cfg::Mtok * cfg::Din];                 // fp32
__device__ float g_h1[cfg::Mtok * cfg::Din];                   // fp32 (residual)
__device__ float g_h1t[cfg::Mtok * cfg::Din];                  // tf32 bits (FFN1 A)
__device__ float g_mid[cfg::Mtok * cfg::Dmid];                 // tf32 bits
__device__ float g_ff[cfg::Mtok * cfg::Din];                   // fp32

// Pre-truncated tf32 copies of inputs + weights
__device__ float g_qt[cfg::Mtok * cfg::Din];
__device__ float g_kt[cfg::Mtok * cfg::Din];
__device__ float g_vt[cfg::Mtok * cfg::Din];
__device__ float g_WQt[cfg::Din * cfg::Din];
__device__ float g_WKt[cfg::Din * cfg::Din];
__device__ float g_WVt[cfg::Din * cfg::Din];
__device__ float g_WOt[cfg::Din * cfg::Din];
__device__ float g_W1t[cfg::Din * cfg::Dmid];
__device__ float g_W2t[cfg::Dmid * cfg::Din];

// ---------------------------------------------------------------------------
// cp.async helpers
// ---------------------------------------------------------------------------
__device__ __forceinline__ void cpa16(void* smem, const void* gmem) {
    unsigned sa = (unsigned)__cvta_generic_to_shared(smem);
    asm volatile("cp.async.cg.shared.global [%0], [%1], 16;" :: "r"(sa), "l"(gmem));
}
__device__ __forceinline__ void cpa_commit() {
    asm volatile("cp.async.commit_group;");
}
template <int N>
__device__ __forceinline__ void cpa_wait() {
    asm volatile("cp.async.wait_group %0;" :: "n"(N));
}

__device__ __forceinline__ unsigned f2tf(float f) {
    unsigned u;
    asm("cvt.rna.tf32.f32 %0, %1;" : "=r"(u) : "f"(f));
    return u;
}
__device__ __forceinline__ float f2tf_f(float f) { return __uint_as_float(f2tf(f)); }

// mma.m16n8k8 tf32: A 4 regs, B 2 regs, C/D 4 floats (in-place accumulate)
__device__ __forceinline__ void mma_tf32_16n8k8(float d[4], const unsigned a[4],
                                                const unsigned b[2]) {
    asm volatile(
        "mma.sync.aligned.m16n8k8.row.col.f32.tf32.tf32.f32 "
        "{%0,%1,%2,%3}, {%4,%5,%6,%7}, {%8,%9}, {%0,%1,%2,%3};"
        : "+f"(d[0]), "+f"(d[1]), "+f"(d[2]), "+f"(d[3])
        : "r"(a[0]), "r"(a[1]), "r"(a[2]), "r"(a[3]), "r"(b[0]), "r"(b[1]));
}

// ---------------------------------------------------------------------------
// Single-launch fp32 -> tf32-bits conversion for all 9 tensors.
// ---------------------------------------------------------------------------
struct Cvt9 {
    const float* s[9];
    float*       d[9];
    int          n[9];
};

__global__ __launch_bounds__(256) void cvt_all_kernel(Cvt9 a)
{
    const int tid = blockIdx.x * 256 + threadIdx.x;
    const int stride = gridDim.x * 256;
#pragma unroll
    for (int seg = 0; seg < 9; seg++) {
        const float4* src = (const float4*)a.s[seg];
        float4*       dst = (float4*)a.d[seg];
        const int n4 = a.n[seg] >> 2;
        for (int i = tid; i < n4; i += stride) {
            float4 v = src[i];
            v.x = f2tf_f(v.x); v.y = f2tf_f(v.y);
            v.z = f2tf_f(v.z); v.w = f2tf_f(v.w);
            dst[i] = v;
        }
    }
}

// ---------------------------------------------------------------------------
// tf32 GEMM, operands PRE-TRUNCATED to tf32 bits (no cvt in mainloop).
// C[M,N] = A[M,K] * B[K,N], fp32 accum.
// Block tile 128x256x16, 256 threads (8 warps, 2x4), warp tile 64x64.
// 4-stage cp.async pipeline, ONE __syncthreads per k-iter, 1 CTA/SM.
// Epilogues: 0 = plain fp32, 2 = head-split [b,h,l,64] + tf32 cvt,
//            3 = relu + tf32 cvt.
// ---------------------------------------------------------------------------
constexpr int BM = 128, BN = 256, BK = 16;
constexpr int ALD = BK + 4;        // 20
constexpr int BLD = BN + 4;        // 260
constexpr int AS_F = BM * ALD;     // 2560 floats / stage
constexpr int BS_F = BK * BLD;     // 4160 floats / stage
constexpr int GST  = 4;
constexpr size_t GEMM_SMEM = (size_t)GST * (AS_F + BS_F) * sizeof(float);  // 107,520 B

template <int EPI>
__device__ __forceinline__ void gemm_dev(
    const float* __restrict__ A, const float* __restrict__ Bw,
    float* __restrict__ C, int M, int N, int K)
{
    extern __shared__ float gsm[];
    float* As = gsm;
    float* Bs = gsm + GST * AS_F;

    const int tid  = threadIdx.x;
    const int bm   = blockIdx.y * BM;
    const int bn   = blockIdx.x * BN;
    const int warp = tid >> 5;
    const int lane = tid & 31;
    const int wr   = warp >> 2;   // 0..1
    const int wc   = warp & 3;    // 0..3

    wmma::fragment<wmma::accumulator, 16, 16, 8, float> acc[4][4];
#pragma unroll
    for (int mi = 0; mi < 4; mi++)
#pragma unroll
        for (int ni = 0; ni < 4; ni++) wmma::fill_fragment(acc[mi][ni], 0.0f);

    auto load_tiles = [&](int buf, int kt) {
        const int k0 = kt * BK;
        float* Ab = As + buf * AS_F;
        float* Bb = Bs + buf * BS_F;
        // A tile: 128 x 16 floats = 512 float4, 2 per thread
#pragma unroll
        for (int i = 0; i < 2; i++) {
            int lin = tid + i * 256;          // 0..511
            int r   = lin >> 2;
            int c4  = (lin & 3) * 4;
            cpa16(Ab + r * ALD + c4, A + (size_t)(bm + r) * K + k0 + c4);
        }
        // B tile: 16 x 256 floats = 1024 float4, 4 per thread
#pragma unroll
        for (int i = 0; i < 4; i++) {
            int lin = tid + i * 256;          // 0..1023
            int r   = lin >> 6;               // 0..15
            int c4  = (lin & 63) * 4;         // 0..252
            cpa16(Bb + r * BLD + c4, Bw + (size_t)(k0 + r) * N + bn + c4);
        }
        cpa_commit();
    };

    const int nkt = K / BK;       // >= 32 for all our shapes
    load_tiles(0, 0);
    load_tiles(1, 1);
    load_tiles(2, 2);

    for (int kt = 0; kt < nkt; kt++) {
        if (kt + 2 < nkt)      cpa_wait<2>();
        else if (kt + 1 < nkt) cpa_wait<1>();
        else                   cpa_wait<0>();
        __syncthreads();
        // Prefetch stage kt+3 (that buffer was read in iter kt-1; all warps
        // have passed this iteration's barrier, so its reads are done).
        if (kt + 3 < nkt) load_tiles((kt + 3) % GST, kt + 3);

        const int buf = kt % GST;
        const float* Ab = As + buf * AS_F;
        const float* Bb = Bs + buf * BS_F;
#pragma unroll
        for (int ks = 0; ks < 2; ks++) {
            wmma::fragment<wmma::matrix_a, 16, 16, 8, wmma::precision::tf32, wmma::row_major> af[4];
            wmma::fragment<wmma::matrix_b, 16, 16, 8, wmma::precision::tf32, wmma::row_major> bf[4];
#pragma unroll
            for (int mi = 0; mi < 4; mi++)
                wmma::load_matrix_sync(af[mi], Ab + (wr * 64 + mi * 16) * ALD + ks * 8, ALD);
#pragma unroll
            for (int ni = 0; ni < 4; ni++)
                wmma::load_matrix_sync(bf[ni], Bb + (ks * 8) * BLD + wc * 64 + ni * 16, BLD);
#pragma unroll
            for (int mi = 0; mi < 4; mi++)
#pragma unroll
                for (int ni = 0; ni < 4; ni++)
                    wmma::mma_sync(acc[mi][ni], af[mi], bf[ni], acc[mi][ni]);
        }
    }
    __syncthreads();   // protect smem reuse by epilogue staging

    float* stg = gsm + warp * (16 * 20);
#pragma unroll
    for (int mi = 0; mi < 4; mi++) {
#pragma unroll
        for (int ni = 0; ni < 4; ni++) {
            wmma::store_matrix_sync(stg, acc[mi][ni], 20, wmma::mem_row_major);
            __syncwarp();
#pragma unroll
            for (int e = 0; e < 8; e++) {
                int idx = lane + e * 32;
                int r = idx >> 4, c = idx & 15;
                int gr = bm + wr * 64 + mi * 16 + r;
                int gc = bn + wc * 64 + ni * 16 + c;
                float v = stg[r * 20 + c];
                if (EPI == 3) v = fmaxf(v, 0.0f);
                if (EPI == 2) {
                    int b = gr >> 11;              // Ls = 2048
                    int l = gr & (cfg::Ls - 1);
                    int h = gc >> 6;               // Dh = 64
                    int d = gc & 63;
                    C[(((size_t)(b * cfg::Hh + h) * cfg::Ls + l) << 6) + d] = f2tf_f(v);
                } else if (EPI == 3) {
                    C[(size_t)gr * N + gc] = f2tf_f(v);
                } else {
                    C[(size_t)gr * N + gc] = v;
                }
            }
            __syncwarp();
        }
    }
}

template <int EPI>
__global__ __launch_bounds__(256, 1) void gemm_tf32(
    const float* __restrict__ A, const float* __restrict__ Bw,
    float* __restrict__ C, int M, int N, int K)
{
    gemm_dev<EPI>(A, Bw, C, M, N, K);
}

// Fused QKV projection: blockIdx.z selects (input, weight, output) triple.
__global__ __launch_bounds__(256, 1) void gemm_qkv(
    const float* __restrict__ q, const float* __restrict__ k,
    const float* __restrict__ v,
    const float* __restrict__ WQ, const float* __restrict__ WK,
    const float* __restrict__ WV,
    float* __restrict__ Qd, float* __restrict__ Kd, float* __restrict__ Vd)
{
    const int z = blockIdx.z;
    const float* A = (z == 0) ? q : (z == 1) ? k : v;
    const float* W = (z == 0) ? WQ : (z == 1) ? WK : WV;
    float* C       = (z == 0) ? Qd : (z == 1) ? Kd : Vd;
    gemm_dev<2>(A, W, C, cfg::Mtok, cfg::Din, cfg::Din);
}

// ---------------------------------------------------------------------------
// Flash attention: raw mma.m16n8k8.tf32, S and O register-resident.
// Q/K/V arrive PRE-TRUNCATED to tf32 bits, so the mainloop has no
// conversion pass: 1 barrier per kv-tile.
// Block = (b, h, 128 q-rows); 256 threads (8 warps), warp owns 16 rows.
// ---------------------------------------------------------------------------
constexpr int FQ2  = 128;
constexpr int QSTR = 68;   // 68 % 32 == 4 -> conflict-free Q/K frag loads
constexpr int KSTR = 68;
constexpr int VSTR = 72;   // 72 % 32 == 8 -> conflict-free V frag loads

constexpr int SM_Q = 0;                        // 128*68
constexpr int SM_K = SM_Q + FQ2 * QSTR;        // 2 * 64*68
constexpr int SM_V = SM_K + 2 * 64 * KSTR;     // 2 * 64*72
constexpr int FLASH2_FLOATS = SM_V + 2 * 64 * VSTR;           // 26624
constexpr size_t FLASH2_SMEM = (size_t)FLASH2_FLOATS * sizeof(float);  // 106,496 B

__global__ __launch_bounds__(256, 2) void flash2_kernel(
    const float* __restrict__ Qg, const float* __restrict__ Kg,
    const float* __restrict__ Vg, const float* __restrict__ maskg,
    float* __restrict__ Og)
{
    extern __shared__ float sm[];
    float* Qs = sm + SM_Q;
    float* Ks = sm + SM_K;
    float* Vs = sm + SM_V;

    const int tid  = threadIdx.x;
    const int warp = tid >> 5;
    const int lane = tid & 31;
    const int g    = lane >> 2;     // fragment row group (0..7)
    const int q    = lane & 3;      // thread-in-group (0..3)
    const int b    = blockIdx.z;
    const int h    = blockIdx.y;
    const int q0   = blockIdx.x * FQ2;
    const int wrow = warp * 16;

    const size_t bh = (size_t)(b * cfg::Hh + h) * cfg::Ls;
    const float* Qbase = Qg + (bh + q0) * cfg::Dh;

    // Q: 128 rows x 16 float4 via cp.async
#pragma unroll
    for (int i = 0; i < 8; i++) {
        int lin = tid + i * 256;
        int r = lin >> 4, c4 = (lin & 15) * 4;
        cpa16(&Qs[r * QSTR + c4], Qbase + r * cfg::Dh + c4);
    }

    auto loadKV = [&](int buf, int kt) {
        const float* Kb = Kg + (bh + kt * 64) * cfg::Dh;
        const float* Vb = Vg + (bh + kt * 64) * cfg::Dh;
#pragma unroll
        for (int i = 0; i < 4; i++) {
            int lin = tid + i * 256;
            int r = lin >> 4, c4 = (lin & 15) * 4;
            cpa16(&Ks[buf * 64 * KSTR + r * KSTR + c4], Kb + r * cfg::Dh + c4);
            cpa16(&Vs[buf * 64 * VSTR + r * VSTR + c4], Vb + r * cfg::Dh + c4);
        }
    };
    loadKV(0, 0);
    cpa_commit();

    // Register state: rows (wrow+g) and (wrow+g+8)
    float m0 = -CUDART_INF_F, m1 = -CUDART_INF_F;
    float l0 = 0.0f, l1 = 0.0f;
    float o[8][4];
#pragma unroll
    for (int t = 0; t < 8; t++)
#pragma unroll
        for (int e = 0; e < 4; e++) o[t][e] = 0.0f;

    const float* mrow0 = maskg + ((size_t)b * cfg::Ls + q0 + wrow + g) * cfg::Ls;
    const float* mrow1 = mrow0 + 8 * (size_t)cfg::Ls;

    const unsigned* Qu = (const unsigned*)Qs;
    const int srcA = (lane & 28) | (q >> 1);   // owner of P col q within quad
    const int srcB = srcA + 2;                 // owner of P col q+4
    const bool odd = (q & 1) != 0;

    for (int kt = 0; kt < cfg::Ls / 64; kt++) {
        const int cur = kt & 1;
        cpa_wait<0>();
        __syncthreads();
        if (kt + 1 < cfg::Ls / 64) { loadKV(cur ^ 1, kt + 1); cpa_commit(); }

        const unsigned* Ku = (const unsigned*)(Ks + cur * 64 * KSTR);
        const unsigned* Vu = (const unsigned*)(Vs + cur * 64 * VSTR);

        // ---- S = Q K^T (registers) ----
        float s[8][4];
#pragma unroll
        for (int t = 0; t < 8; t++)
#pragma unroll
            for (int e = 0; e < 4; e++) s[t][e] = 0.0f;

#pragma unroll
        for (int j = 0; j < 8; j++) {              // k over dh
            unsigned a[4];
            a[0] = Qu[(wrow + g) * QSTR + j * 8 + q];
            a[1] = Qu[(wrow + g + 8) * QSTR + j * 8 + q];
            a[2] = Qu[(wrow + g) * QSTR + j * 8 + q + 4];
            a[3] = Qu[(wrow + g + 8) * QSTR + j * 8 + q + 4];
#pragma unroll
            for (int t = 0; t < 8; t++) {          // n over kv rows
                unsigned bf[2];
                bf[0] = Ku[(t * 8 + g) * KSTR + j * 8 + q];
                bf[1] = Ku[(t * 8 + g) * KSTR + j * 8 + q + 4];
                mma_tf32_16n8k8(s[t], a, bf);
            }
        }

        // ---- scale + mask ----
        const int kcol = kt * 64;
#pragma unroll
        for (int t = 0; t < 8; t++) {
            float2 mk0 = *(const float2*)(mrow0 + kcol + t * 8 + 2 * q);
            float2 mk1 = *(const float2*)(mrow1 + kcol + t * 8 + 2 * q);
            s[t][0] = s[t][0] * 0.125f + mk0.x;
            s[t][1] = s[t][1] * 0.125f + mk0.y;
            s[t][2] = s[t][2] * 0.125f + mk1.x;
            s[t][3] = s[t][3] * 0.125f + mk1.y;
        }

        // ---- online softmax (register + 2 shfl per row) ----
        float mx0 = -CUDART_INF_F, mx1 = -CUDART_INF_F;
#pragma unroll
        for (int t = 0; t < 8; t++) {
            mx0 = fmaxf(mx0, fmaxf(s[t][0], s[t][1]));
            mx1 = fmaxf(mx1, fmaxf(s[t][2], s[t][3]));
        }
        mx0 = fmaxf(mx0, __shfl_xor_sync(0xffffffffu, mx0, 1));
        mx0 = fmaxf(mx0, __shfl_xor_sync(0xffffffffu, mx0, 2));
        mx1 = fmaxf(mx1, __shfl_xor_sync(0xffffffffu, mx1, 1));
        mx1 = fmaxf(mx1, __shfl_xor_sync(0xffffffffu, mx1, 2));

        const float m0n = fmaxf(m0, mx0);
        const float m1n = fmaxf(m1, mx1);
        const float c0  = __expf(m0 - m0n);
        const float c1  = __expf(m1 - m1n);

        float sum0 = 0.0f, sum1 = 0.0f;
#pragma unroll
        for (int t = 0; t < 8; t++) {
            s[t][0] = __expf(s[t][0] - m0n);
            s[t][1] = __expf(s[t][1] - m0n);
            s[t][2] = __expf(s[t][2] - m1n);
            s[t][3] = __expf(s[t][3] - m1n);
            sum0 += s[t][0] + s[t][1];
            sum1 += s[t][2] + s[t][3];
        }
        sum0 += __shfl_xor_sync(0xffffffffu, sum0, 1);
        sum0 += __shfl_xor_sync(0xffffffffu, sum0, 2);
        sum1 += __shfl_xor_sync(0xffffffffu, sum1, 1);
        sum1 += __shfl_xor_sync(0xffffffffu, sum1, 2);

        l0 = l0 * c0 + sum0;
        l1 = l1 * c1 + sum1;
        m0 = m0n;
        m1 = m1n;

        // ---- rescale O (registers) ----
#pragma unroll
        for (int t = 0; t < 8; t++) {
            o[t][0] *= c0; o[t][1] *= c0;
            o[t][2] *= c1; o[t][3] *= c1;
        }

        // ---- O += P V.  P A-fragments built from s[j] via quad shuffles ----
#pragma unroll
        for (int j = 0; j < 8; j++) {              // k over kv rows (chunk j)
            float u0 = __shfl_sync(0xffffffffu, s[j][0], srcA);
            float u1 = __shfl_sync(0xffffffffu, s[j][1], srcA);
            float v0 = __shfl_sync(0xffffffffu, s[j][0], srcB);
            float v1 = __shfl_sync(0xffffffffu, s[j][1], srcB);
            float w0 = __shfl_sync(0xffffffffu, s[j][2], srcA);
            float w1 = __shfl_sync(0xffffffffu, s[j][3], srcA);
            float x0 = __shfl_sync(0xffffffffu, s[j][2], srcB);
            float x1 = __shfl_sync(0xffffffffu, s[j][3], srcB);
            unsigned a[4];
            a[0] = f2tf(odd ? u1 : u0);            // P[g][8j+q]
            a[1] = f2tf(odd ? w1 : w0);            // P[g+8][8j+q]
            a[2] = f2tf(odd ? v1 : v0);            // P[g][8j+q+4]
            a[3] = f2tf(odd ? x1 : x0);            // P[g+8][8j+q+4]
#pragma unroll
            for (int t = 0; t < 8; t++) {          // n over dh
                unsigned bf[2];
                bf[0] = Vu[(j * 8 + q) * VSTR + t * 8 + g];
                bf[1] = Vu[(j * 8 + q + 4) * VSTR + t * 8 + g];
                mma_tf32_16n8k8(o[t], a, bf);
            }
        }
    }

    // ---- normalize, tf32-truncate (feeds WO GEMM) & write concat layout ----
    const float inv0 = 1.0f / l0;
    const float inv1 = 1.0f / l1;
    float* orow0 = Og + ((size_t)b * cfg::Ls + q0 + wrow + g) * cfg::Din + h * cfg::Dh;
    float* orow1 = orow0 + 8 * (size_t)cfg::Din;
#pragma unroll
    for (int t = 0; t < 8; t++) {
        float2 w0 = { f2tf_f(o[t][0] * inv0), f2tf_f(o[t][1] * inv0) };
        float2 w1 = { f2tf_f(o[t][2] * inv1), f2tf_f(o[t][3] * inv1) };
        *(float2*)&orow0[t * 8 + 2 * q] = w0;
        *(float2*)&orow1[t * 8 + 2 * q] = w1;
    }
}

// ---------------------------------------------------------------------------
// Fused residual-add + LayerNorm over last dim (512). One block per row.
// Optionally also writes a tf32-truncated copy (A operand for next GEMM).
// ---------------------------------------------------------------------------
template <bool T32>
__global__ __launch_bounds__(128) void ln_add_kernel(
    const float* __restrict__ x, const float* __restrict__ y,
    float* __restrict__ out, float* __restrict__ out_t)
{
    const int row = blockIdx.x;
    const float* px = x + (size_t)row * cfg::Din;
    const float* py = y + (size_t)row * cfg::Din;

    float v[4];
    float s = 0.0f, sq = 0.0f;
#pragma unroll
    for (int i = 0; i < 4; i++) {
        int c = threadIdx.x + i * 128;
        v[i] = px[c] + py[c];
        s  += v[i];
        sq += v[i] * v[i];
    }
#pragma unroll
    for (int o = 16; o > 0; o >>= 1) {
        s  += __shfl_xor_sync(0xffffffffu, s, o);
        sq += __shfl_xor_sync(0xffffffffu, sq, o);
    }
    __shared__ float ws[4], wq[4];
    __shared__ float mean_s, inv_s;
    const int warp = threadIdx.x >> 5, lane = threadIdx.x & 31;
    if (lane == 0) { ws[warp] = s; wq[warp] = sq; }
    __syncthreads();
    if (threadIdx.x == 0) {
        float S = ws[0] + ws[1] + ws[2] + ws[3];
        float Q = wq[0] + wq[1] + wq[2] + wq[3];
        float mean = S * (1.0f / cfg::Din);
        float var  = Q * (1.0f / cfg::Din) - mean * mean;
        mean_s = mean;
        inv_s  = rsqrtf(var + 1e-5f);
    }
    __syncthreads();
    float* po = out + (size_t)row * cfg::Din;
    float* pt = out_t + (size_t)row * cfg::Din;
#pragma unroll
    for (int i = 0; i < 4; i++) {
        int c = threadIdx.x + i * 128;
        float r = (v[i] - mean_s) * inv_s;
        po[c] = r;
        if (T32) pt[c] = f2tf_f(r);
    }
}

// ---------------------------------------------------------------------------
// kernel_launch
// ---------------------------------------------------------------------------
extern "C" void kernel_launch(void* const* d_in, const int* in_sizes, int n_in,
                              void* d_out, int out_size)
{
    const float* query = (const float*)d_in[0];
    const float* key   = (const float*)d_in[1];
    const float* value = (const float*)d_in[2];
    const float* mask  = (const float*)d_in[3];
    const float* WQ    = (const float*)d_in[4];
    const float* WK    = (const float*)d_in[5];
    const float* WV    = (const float*)d_in[6];
    const float* WO    = (const float*)d_in[7];
    const float* W1    = (const float*)d_in[8];
    const float* W2    = (const float*)d_in[9];
    float* out = (float*)d_out;

    float *Qd, *Kd, *Vd, *attn, *proj, *h1, *h1t, *mid, *ff;
    float *qt, *kt, *vt, *WQt, *WKt, *WVt, *WOt, *W1t, *W2t;
    cudaGetSymbolAddress((void**)&Qd,   g_Q);
    cudaGetSymbolAddress((void**)&Kd,   g_K);
    cudaGetSymbolAddress((void**)&Vd,   g_V);
    cudaGetSymbolAddress((void**)&attn, g_attn);
    cudaGetSymbolAddress((void**)&proj, g_proj);
    cudaGetSymbolAddress((void**)&h1,   g_h1);
    cudaGetSymbolAddress((void**)&h1t,  g_h1t);
    cudaGetSymbolAddress((void**)&mid,  g_mid);
    cudaGetSymbolAddress((void**)&ff,   g_ff);
    cudaGetSymbolAddress((void**)&qt,   g_qt);
    cudaGetSymbolAddress((void**)&kt,   g_kt);
    cudaGetSymbolAddress((void**)&vt,   g_vt);
    cudaGetSymbolAddress((void**)&WQt,  g_WQt);
    cudaGetSymbolAddress((void**)&WKt,  g_WKt);
    cudaGetSymbolAddress((void**)&WVt,  g_WVt);
    cudaGetSymbolAddress((void**)&WOt,  g_WOt);
    cudaGetSymbolAddress((void**)&W1t,  g_W1t);
    cudaGetSymbolAddress((void**)&W2t,  g_W2t);

    cudaFuncSetAttribute(flash2_kernel, cudaFuncAttributeMaxDynamicSharedMemorySize,
                         (int)FLASH2_SMEM);
    cudaFuncSetAttribute(gemm_tf32<0>, cudaFuncAttributeMaxDynamicSharedMemorySize,
                         (int)GEMM_SMEM);
    cudaFuncSetAttribute(gemm_tf32<3>, cudaFuncAttributeMaxDynamicSharedMemorySize,
                         (int)GEMM_SMEM);
    cudaFuncSetAttribute(gemm_qkv, cudaFuncAttributeMaxDynamicSharedMemorySize,
                         (int)GEMM_SMEM);

    // -- one-launch tf32 truncation of raw inputs + weights --
    const int nIn = cfg::Mtok * cfg::Din;      // 4,194,304
    const int nWs = cfg::Din * cfg::Din;       // 262,144
    const int nWf = cfg::Din * cfg::Dmid;      // 1,048,576
    Cvt9 cv;
    cv.s[0] = query; cv.d[0] = qt;  cv.n[0] = nIn;
    cv.s[1] = key;   cv.d[1] = kt;  cv.n[1] = nIn;
    cv.s[2] = value; cv.d[2] = vt;  cv.n[2] = nIn;
    cv.s[3] = WQ;    cv.d[3] = WQt; cv.n[3] = nWs;
    cv.s[4] = WK;    cv.d[4] = WKt; cv.n[4] = nWs;
    cv.s[5] = WV;    cv.d[5] = WVt; cv.n[5] = nWs;
    cv.s[6] = WO;    cv.d[6] = WOt; cv.n[6] = nWs;
    cv.s[7] = W1;    cv.d[7] = W1t; cv.n[7] = nWf;
    cv.s[8] = W2;    cv.d[8] = W2t; cv.n[8] = nWf;
    cvt_all_kernel<<<2048, 256>>>(cv);

    const dim3 gProj(cfg::Din / BN, cfg::Mtok / BM);        // (2, 64)
    const dim3 gQkv (cfg::Din / BN, cfg::Mtok / BM, 3);     // (2, 64, 3)
    const dim3 gFfn1(cfg::Dmid / BN, cfg::Mtok / BM);       // (8, 64)

    // Fused QKV projections (head-split + tf32 epilogue)
    gemm_qkv<<<gQkv, 256, GEMM_SMEM>>>(qt, kt, vt, WQt, WKt, WVt, Qd, Kd, Vd);

    // Flash attention (consumes tf32 Q/K/V, emits tf32 attn)
    dim3 gFlash(cfg::Ls / FQ2, cfg::Hh, cfg::Bb);           // (16, 8, 4)
    flash2_kernel<<<gFlash, 256, FLASH2_SMEM>>>(Qd, Kd, Vd, mask, attn);

    // Output projection + residual LN (fp32 out + tf32 copy for FFN1)
    gemm_tf32<0><<<gProj, 256, GEMM_SMEM>>>(attn, WOt, proj, cfg::Mtok, cfg::Din, cfg::Din);
    ln_add_kernel<true><<<cfg::Mtok, 128>>>(query, proj, h1, h1t);

    // FFN (FFN1: relu + tf32 epilogue; FFN2: fp32)
    gemm_tf32<3><<<gFfn1, 256, GEMM_SMEM>>>(h1t, W1t, mid, cfg::Mtok, cfg::Dmid, cfg::Din);
    gemm_tf32<0><<<gProj, 256, GEMM_SMEM>>>(mid, W2t, ff, cfg::Mtok, cfg::Din, cfg::Dmid);
    ln_add_kernel<false><<<cfg::Mtok, 128>>>(h1, ff, out, out);

    (void)in_sizes; (void)n_in; (void)out_size;
}

// round 14
// speedup vs baseline: 5.0542x; 1.5564x over previous
#include <cuda_runtime.h>
#include <math_constants.h>
#include <cstdint>
#include <cstddef>

// ---------------------------------------------------------------------------
// Problem constants
// ---------------------------------------------------------------------------
namespace cfg {
constexpr int Bb   = 4;
constexpr int Ls   = 2048;
constexpr int Din  = 512;
constexpr int Hh   = 8;
constexpr int Dh   = 64;
constexpr int Dmid = 2048;
constexpr int Mtok = Bb * Ls;   // 8192 tokens
}

// ---------------------------------------------------------------------------
// Scratch (static device globals — no allocations anywhere)
// ---------------------------------------------------------------------------
__device__ float g_Q[cfg::Bb * cfg::Hh * cfg::Ls * cfg::Dh];   // [b,h,l,d] tf32 bits
__device__ float g_K[cfg::Bb * cfg::Hh * cfg::Ls * cfg::Dh];   // tf32 bits
__device__ float g_V[cfg::Bb * cfg::Hh * cfg::Ls * cfg::Dh];   // tf32 bits
__device__ float g_attn[cfg::Mtok * cfg::Din];                 // tf32 bits
__device__ float g_proj[cfg::Mtok * cfg::Din];                 // fp32
__device__ float g_h1[cfg::Mtok * cfg::Din];                   // fp32 (residual)
__device__ float g_h1t[cfg::Mtok * cfg::Din];                  // tf32 bits (FFN1 A)
__device__ float g_mid[cfg::Mtok * cfg::Dmid];                 // tf32 bits
__device__ float g_ff[cfg::Mtok * cfg::Din];                   // fp32

// Pre-truncated tf32 copies of inputs + weights (weights stay [K][N] row-major)
__device__ float g_qt[cfg::Mtok * cfg::Din];
__device__ float g_kt[cfg::Mtok * cfg::Din];
__device__ float g_vt[cfg::Mtok * cfg::Din];
__device__ float g_WQt[cfg::Din * cfg::Din];
__device__ float g_WKt[cfg::Din * cfg::Din];
__device__ float g_WVt[cfg::Din * cfg::Din];
__device__ float g_WOt[cfg::Din * cfg::Din];
__device__ float g_W1t[cfg::Din * cfg::Dmid];
__device__ float g_W2t[cfg::Dmid * cfg::Din];

// ---------------------------------------------------------------------------
// PTX helpers
// ---------------------------------------------------------------------------
__device__ __forceinline__ void cpa16(void* smem, const void* gmem) {
    unsigned sa = (unsigned)__cvta_generic_to_shared(smem);
    asm volatile("cp.async.cg.shared.global [%0], [%1], 16;" :: "r"(sa), "l"(gmem));
}
__device__ __forceinline__ void cpa_commit() {
    asm volatile("cp.async.commit_group;");
}
template <int N>
__device__ __forceinline__ void cpa_wait() {
    asm volatile("cp.async.wait_group %0;" :: "n"(N));
}

__device__ __forceinline__ unsigned f2tf(float f) {
    unsigned u;
    asm("cvt.rna.tf32.f32 %0, %1;" : "=r"(u) : "f"(f));
    return u;
}
__device__ __forceinline__ float f2tf_f(float f) { return __uint_as_float(f2tf(f)); }

// mma.m16n8k8 tf32: A 4 regs, B 2 regs, C/D 4 floats (in-place accumulate)
__device__ __forceinline__ void mma_tf32_16n8k8(float d[4], const unsigned a[4],
                                                const unsigned b[2]) {
    asm volatile(
        "mma.sync.aligned.m16n8k8.row.col.f32.tf32.tf32.f32 "
        "{%0,%1,%2,%3}, {%4,%5,%6,%7}, {%8,%9}, {%0,%1,%2,%3};"
        : "+f"(d[0]), "+f"(d[1]), "+f"(d[2]), "+f"(d[3])
        : "r"(a[0]), "r"(a[1]), "r"(a[2]), "r"(a[3]), "r"(b[0]), "r"(b[1]));
}

// ---------------------------------------------------------------------------
// Single-launch fp32 -> tf32-bits conversion for all 9 tensors.
// ---------------------------------------------------------------------------
struct Cvt9 {
    const float* s[9];
    float*       d[9];
    int          n[9];
};

__global__ __launch_bounds__(256) void cvt_all_kernel(Cvt9 a)
{
    const int tid = blockIdx.x * 256 + threadIdx.x;
    const int stride = gridDim.x * 256;
#pragma unroll
    for (int seg = 0; seg < 9; seg++) {
        const float4* src = (const float4*)a.s[seg];
        float4*       dst = (float4*)a.d[seg];
        const int n4 = a.n[seg] >> 2;
        for (int i = tid; i < n4; i += stride) {
            float4 v = src[i];
            v.x = f2tf_f(v.x); v.y = f2tf_f(v.y);
            v.z = f2tf_f(v.z); v.w = f2tf_f(v.w);
            dst[i] = v;
        }
    }
}

// ---------------------------------------------------------------------------
// Raw-mma tf32 GEMM (flash-style operand fetch).
// C[M,N] = A[M,K] * B[K,N], fp32 accum, operands pre-truncated tf32 bits.
// Block tile 128x128x32, 256 threads (8 warps, 2x4), warp tile 64x32.
// 3-stage cp.async, ONE barrier/iter, 2 CTAs/SM (16 warps).
// A-frag LDS bank = (4g+q)%32 all-distinct (ALD%32==4).
// B-frag LDS bank = (8q+g)%32 all-distinct (BLD%32==8).
// Epilogues: 0 plain fp32, 2 head-split [b,h,l,64]+tf32, 3 relu+tf32.
// ---------------------------------------------------------------------------
constexpr int BM = 128, BN = 128, BK = 32;
constexpr int ALD = BK + 4;        // 36
constexpr int BLD = BN + 8;        // 136
constexpr int AS_F = BM * ALD;     // 4608 floats / stage
constexpr int BS_F = BK * BLD;     // 4352 floats / stage
constexpr int GST  = 3;
constexpr size_t GEMM_SMEM = (size_t)GST * (AS_F + BS_F) * sizeof(float);  // 107,520 B

template <int EPI>
__device__ __forceinline__ void gemm_dev(
    const float* __restrict__ A, const float* __restrict__ Bw,
    float* __restrict__ C, int M, int N, int K)
{
    extern __shared__ float gsm[];
    float* As = gsm;
    float* Bs = gsm + GST * AS_F;

    const int tid  = threadIdx.x;
    const int bm   = blockIdx.y * BM;
    const int bn   = blockIdx.x * BN;
    const int warp = tid >> 5;
    const int lane = tid & 31;
    const int g    = lane >> 2;    // 0..7
    const int q    = lane & 3;     // 0..3
    const int wr   = warp >> 2;    // 0..1  (rows wr*64)
    const int wc   = warp & 3;     // 0..3  (cols wc*32)

    float acc[4][4][4];
#pragma unroll
    for (int mi = 0; mi < 4; mi++)
#pragma unroll
        for (int ni = 0; ni < 4; ni++)
#pragma unroll
            for (int e = 0; e < 4; e++) acc[mi][ni][e] = 0.0f;

    auto load_tiles = [&](int buf, int kt) {
        const int k0 = kt * BK;
        float* Ab = As + buf * AS_F;
        float* Bb = Bs + buf * BS_F;
        // A tile: 128 rows x 32 floats = 1024 float4, 4 per thread
#pragma unroll
        for (int i = 0; i < 4; i++) {
            int lin = tid + i * 256;          // 0..1023
            int r   = lin >> 3;               // 0..127
            int c4  = (lin & 7) * 4;          // 0..28
            cpa16(Ab + r * ALD + c4, A + (size_t)(bm + r) * K + k0 + c4);
        }
        // B tile: 32 rows x 128 floats = 1024 float4, 4 per thread
#pragma unroll
        for (int i = 0; i < 4; i++) {
            int lin = tid + i * 256;
            int r   = lin >> 5;               // 0..31
            int c4  = (lin & 31) * 4;         // 0..124
            cpa16(Bb + r * BLD + c4, Bw + (size_t)(k0 + r) * N + bn + c4);
        }
        cpa_commit();
    };

    const int nkt = K / BK;       // >= 16 for all our shapes
    load_tiles(0, 0);
    load_tiles(1, 1);

    for (int kt = 0; kt < nkt; kt++) {
        if (kt + 1 < nkt) cpa_wait<1>(); else cpa_wait<0>();
        __syncthreads();
        if (kt + 2 < nkt) load_tiles((kt + 2) % GST, kt + 2);

        const int buf = kt % GST;
        const unsigned* Au = (const unsigned*)(As + buf * AS_F);
        const unsigned* Bu = (const unsigned*)(Bs + buf * BS_F);

#pragma unroll
        for (int j = 0; j < 4; j++) {             // k8 chunks within BK=32
            const int k0 = j * 8;
            unsigned bfr[4][2];
#pragma unroll
            for (int ni = 0; ni < 4; ni++) {
                const int n0 = wc * 32 + ni * 8;
                bfr[ni][0] = Bu[(k0 + q) * BLD + n0 + g];
                bfr[ni][1] = Bu[(k0 + q + 4) * BLD + n0 + g];
            }
#pragma unroll
            for (int mi = 0; mi < 4; mi++) {
                const int m0 = wr * 64 + mi * 16;
                unsigned a[4];
                a[0] = Au[(m0 + g) * ALD + k0 + q];
                a[1] = Au[(m0 + g + 8) * ALD + k0 + q];
                a[2] = Au[(m0 + g) * ALD + k0 + q + 4];
                a[3] = Au[(m0 + g + 8) * ALD + k0 + q + 4];
#pragma unroll
                for (int ni = 0; ni < 4; ni++)
                    mma_tf32_16n8k8(acc[mi][ni], a, bfr[ni]);
            }
        }
    }

    // ---- Epilogue: registers -> gmem directly (no smem staging) ----
    // acc[mi][ni]: d0,d1 = row (m0+g), cols n0+2q, n0+2q+1 ; d2,d3 = row (m0+g+8).
#pragma unroll
    for (int mi = 0; mi < 4; mi++) {
        const int gr0 = bm + wr * 64 + mi * 16 + g;
        const int gr1 = gr0 + 8;
#pragma unroll
        for (int ni = 0; ni < 4; ni++) {
            const int gc = bn + wc * 32 + ni * 8 + 2 * q;
            float d0 = acc[mi][ni][0], d1 = acc[mi][ni][1];
            float d2 = acc[mi][ni][2], d3 = acc[mi][ni][3];
            if (EPI == 3) {
                d0 = fmaxf(d0, 0.0f); d1 = fmaxf(d1, 0.0f);
                d2 = fmaxf(d2, 0.0f); d3 = fmaxf(d3, 0.0f);
            }
            if (EPI == 2) {
                // head-split [b,h,l,64] + tf32; gc even so (d, d+1) stay in-head
                int h = gc >> 6, d = gc & 63;
                int b0 = gr0 >> 11, l0i = gr0 & (cfg::Ls - 1);
                int b1 = gr1 >> 11, l1i = gr1 & (cfg::Ls - 1);
                float2 w0 = { f2tf_f(d0), f2tf_f(d1) };
                float2 w1 = { f2tf_f(d2), f2tf_f(d3) };
                *(float2*)&C[(((size_t)(b0 * cfg::Hh + h) * cfg::Ls + l0i) << 6) + d] = w0;
                *(float2*)&C[(((size_t)(b1 * cfg::Hh + h) * cfg::Ls + l1i) << 6) + d] = w1;
            } else if (EPI == 3) {
                float2 w0 = { f2tf_f(d0), f2tf_f(d1) };
                float2 w1 = { f2tf_f(d2), f2tf_f(d3) };
                *(float2*)&C[(size_t)gr0 * N + gc] = w0;
                *(float2*)&C[(size_t)gr1 * N + gc] = w1;
            } else {
                float2 w0 = { d0, d1 };
                float2 w1 = { d2, d3 };
                *(float2*)&C[(size_t)gr0 * N + gc] = w0;
                *(float2*)&C[(size_t)gr1 * N + gc] = w1;
            }
        }
    }
}

template <int EPI>
__global__ __launch_bounds__(256, 2) void gemm_tf32(
    const float* __restrict__ A, const float* __restrict__ Bw,
    float* __restrict__ C, int M, int N, int K)
{
    gemm_dev<EPI>(A, Bw, C, M, N, K);
}

// Fused QKV projection: blockIdx.z selects (input, weight, output) triple.
__global__ __launch_bounds__(256, 2) void gemm_qkv(
    const float* __restrict__ q, const float* __restrict__ k,
    const float* __restrict__ v,
    const float* __restrict__ WQ, const float* __restrict__ WK,
    const float* __restrict__ WV,
    float* __restrict__ Qd, float* __restrict__ Kd, float* __restrict__ Vd)
{
    const int z = blockIdx.z;
    const float* A = (z == 0) ? q : (z == 1) ? k : v;
    const float* W = (z == 0) ? WQ : (z == 1) ? WK : WV;
    float* C       = (z == 0) ? Qd : (z == 1) ? Kd : Vd;
    gemm_dev<2>(A, W, C, cfg::Mtok, cfg::Din, cfg::Din);
}

// ---------------------------------------------------------------------------
// Flash attention (unchanged from R11: register-resident S/O, m16n8k8 tf32)
// ---------------------------------------------------------------------------
constexpr int FQ2  = 128;
constexpr int QSTR = 68;
constexpr int KSTR = 68;
constexpr int VSTR = 72;

constexpr int SM_Q = 0;
constexpr int SM_K = SM_Q + FQ2 * QSTR;
constexpr int SM_V = SM_K + 2 * 64 * KSTR;
constexpr int FLASH2_FLOATS = SM_V + 2 * 64 * VSTR;
constexpr size_t FLASH2_SMEM = (size_t)FLASH2_FLOATS * sizeof(float);  // 106,496 B

__global__ __launch_bounds__(256, 2) void flash2_kernel(
    const float* __restrict__ Qg, const float* __restrict__ Kg,
    const float* __restrict__ Vg, const float* __restrict__ maskg,
    float* __restrict__ Og)
{
    extern __shared__ float sm[];
    float* Qs = sm + SM_Q;
    float* Ks = sm + SM_K;
    float* Vs = sm + SM_V;

    const int tid  = threadIdx.x;
    const int warp = tid >> 5;
    const int lane = tid & 31;
    const int g    = lane >> 2;
    const int q    = lane & 3;
    const int b    = blockIdx.z;
    const int h    = blockIdx.y;
    const int q0   = blockIdx.x * FQ2;
    const int wrow = warp * 16;

    const size_t bh = (size_t)(b * cfg::Hh + h) * cfg::Ls;
    const float* Qbase = Qg + (bh + q0) * cfg::Dh;

#pragma unroll
    for (int i = 0; i < 8; i++) {
        int lin = tid + i * 256;
        int r = lin >> 4, c4 = (lin & 15) * 4;
        cpa16(&Qs[r * QSTR + c4], Qbase + r * cfg::Dh + c4);
    }

    auto loadKV = [&](int buf, int kt) {
        const float* Kb = Kg + (bh + kt * 64) * cfg::Dh;
        const float* Vb = Vg + (bh + kt * 64) * cfg::Dh;
#pragma unroll
        for (int i = 0; i < 4; i++) {
            int lin = tid + i * 256;
            int r = lin >> 4, c4 = (lin & 15) * 4;
            cpa16(&Ks[buf * 64 * KSTR + r * KSTR + c4], Kb + r * cfg::Dh + c4);
            cpa16(&Vs[buf * 64 * VSTR + r * VSTR + c4], Vb + r * cfg::Dh + c4);
        }
    };
    loadKV(0, 0);
    cpa_commit();

    float m0 = -CUDART_INF_F, m1 = -CUDART_INF_F;
    float l0 = 0.0f, l1 = 0.0f;
    float o[8][4];
#pragma unroll
    for (int t = 0; t < 8; t++)
#pragma unroll
        for (int e = 0; e < 4; e++) o[t][e] = 0.0f;

    const float* mrow0 = maskg + ((size_t)b * cfg::Ls + q0 + wrow + g) * cfg::Ls;
    const float* mrow1 = mrow0 + 8 * (size_t)cfg::Ls;

    const unsigned* Qu = (const unsigned*)Qs;
    const int srcA = (lane & 28) | (q >> 1);
    const int srcB = srcA + 2;
    const bool odd = (q & 1) != 0;

    for (int kt = 0; kt < cfg::Ls / 64; kt++) {
        const int cur = kt & 1;
        cpa_wait<0>();
        __syncthreads();
        if (kt + 1 < cfg::Ls / 64) { loadKV(cur ^ 1, kt + 1); cpa_commit(); }

        const unsigned* Ku = (const unsigned*)(Ks + cur * 64 * KSTR);
        const unsigned* Vu = (const unsigned*)(Vs + cur * 64 * VSTR);

        float s[8][4];
#pragma unroll
        for (int t = 0; t < 8; t++)
#pragma unroll
            for (int e = 0; e < 4; e++) s[t][e] = 0.0f;

#pragma unroll
        for (int j = 0; j < 8; j++) {
            unsigned a[4];
            a[0] = Qu[(wrow + g) * QSTR + j * 8 + q];
            a[1] = Qu[(wrow + g + 8) * QSTR + j * 8 + q];
            a[2] = Qu[(wrow + g) * QSTR + j * 8 + q + 4];
            a[3] = Qu[(wrow + g + 8) * QSTR + j * 8 + q + 4];
#pragma unroll
            for (int t = 0; t < 8; t++) {
                unsigned bf[2];
                bf[0] = Ku[(t * 8 + g) * KSTR + j * 8 + q];
                bf[1] = Ku[(t * 8 + g) * KSTR + j * 8 + q + 4];
                mma_tf32_16n8k8(s[t], a, bf);
            }
        }

        const int kcol = kt * 64;
#pragma unroll
        for (int t = 0; t < 8; t++) {
            float2 mk0 = *(const float2*)(mrow0 + kcol + t * 8 + 2 * q);
            float2 mk1 = *(const float2*)(mrow1 + kcol + t * 8 + 2 * q);
            s[t][0] = s[t][0] * 0.125f + mk0.x;
            s[t][1] = s[t][1] * 0.125f + mk0.y;
            s[t][2] = s[t][2] * 0.125f + mk1.x;
            s[t][3] = s[t][3] * 0.125f + mk1.y;
        }

        float mx0 = -CUDART_INF_F, mx1 = -CUDART_INF_F;
#pragma unroll
        for (int t = 0; t < 8; t++) {
            mx0 = fmaxf(mx0, fmaxf(s[t][0], s[t][1]));
            mx1 = fmaxf(mx1, fmaxf(s[t][2], s[t][3]));
        }
        mx0 = fmaxf(mx0, __shfl_xor_sync(0xffffffffu, mx0, 1));
        mx0 = fmaxf(mx0, __shfl_xor_sync(0xffffffffu, mx0, 2));
        mx1 = fmaxf(mx1, __shfl_xor_sync(0xffffffffu, mx1, 1));
        mx1 = fmaxf(mx1, __shfl_xor_sync(0xffffffffu, mx1, 2));

        const float m0n = fmaxf(m0, mx0);
        const float m1n = fmaxf(m1, mx1);
        const float c0  = __expf(m0 - m0n);
        const float c1  = __expf(m1 - m1n);

        float sum0 = 0.0f, sum1 = 0.0f;
#pragma unroll
        for (int t = 0; t < 8; t++) {
            s[t][0] = __expf(s[t][0] - m0n);
            s[t][1] = __expf(s[t][1] - m0n);
            s[t][2] = __expf(s[t][2] - m1n);
            s[t][3] = __expf(s[t][3] - m1n);
            sum0 += s[t][0] + s[t][1];
            sum1 += s[t][2] + s[t][3];
        }
        sum0 += __shfl_xor_sync(0xffffffffu, sum0, 1);
        sum0 += __shfl_xor_sync(0xffffffffu, sum0, 2);
        sum1 += __shfl_xor_sync(0xffffffffu, sum1, 1);
        sum1 += __shfl_xor_sync(0xffffffffu, sum1, 2);

        l0 = l0 * c0 + sum0;
        l1 = l1 * c1 + sum1;
        m0 = m0n;
        m1 = m1n;

#pragma unroll
        for (int t = 0; t < 8; t++) {
            o[t][0] *= c0; o[t][1] *= c0;
            o[t][2] *= c1; o[t][3] *= c1;
        }

#pragma unroll
        for (int j = 0; j < 8; j++) {
            float u0 = __shfl_sync(0xffffffffu, s[j][0], srcA);
            float u1 = __shfl_sync(0xffffffffu, s[j][1], srcA);
            float v0 = __shfl_sync(0xffffffffu, s[j][0], srcB);
            float v1 = __shfl_sync(0xffffffffu, s[j][1], srcB);
            float w0 = __shfl_sync(0xffffffffu, s[j][2], srcA);
            float w1 = __shfl_sync(0xffffffffu, s[j][3], srcA);
            float x0 = __shfl_sync(0xffffffffu, s[j][2], srcB);
            float x1 = __shfl_sync(0xffffffffu, s[j][3], srcB);
            unsigned a[4];
            a[0] = f2tf(odd ? u1 : u0);
            a[1] = f2tf(odd ? w1 : w0);
            a[2] = f2tf(odd ? v1 : v0);
            a[3] = f2tf(odd ? x1 : x0);
#pragma unroll
            for (int t = 0; t < 8; t++) {
                unsigned bf[2];
                bf[0] = Vu[(j * 8 + q) * VSTR + t * 8 + g];
                bf[1] = Vu[(j * 8 + q + 4) * VSTR + t * 8 + g];
                mma_tf32_16n8k8(o[t], a, bf);
            }
        }
    }

    const float inv0 = 1.0f / l0;
    const float inv1 = 1.0f / l1;
    float* orow0 = Og + ((size_t)b * cfg::Ls + q0 + wrow + g) * cfg::Din + h * cfg::Dh;
    float* orow1 = orow0 + 8 * (size_t)cfg::Din;
#pragma unroll
    for (int t = 0; t < 8; t++) {
        float2 w0 = { f2tf_f(o[t][0] * inv0), f2tf_f(o[t][1] * inv0) };
        float2 w1 = { f2tf_f(o[t][2] * inv1), f2tf_f(o[t][3] * inv1) };
        *(float2*)&orow0[t * 8 + 2 * q] = w0;
        *(float2*)&orow1[t * 8 + 2 * q] = w1;
    }
}

// ---------------------------------------------------------------------------
// Fused residual-add + LayerNorm over last dim (512). One block per row.
// ---------------------------------------------------------------------------
template <bool T32>
__global__ __launch_bounds__(128) void ln_add_kernel(
    const float* __restrict__ x, const float* __restrict__ y,
    float* __restrict__ out, float* __restrict__ out_t)
{
    const int row = blockIdx.x;
    const float* px = x + (size_t)row * cfg::Din;
    const float* py = y + (size_t)row * cfg::Din;

    float v[4];
    float s = 0.0f, sq = 0.0f;
#pragma unroll
    for (int i = 0; i < 4; i++) {
        int c = threadIdx.x + i * 128;
        v[i] = px[c] + py[c];
        s  += v[i];
        sq += v[i] * v[i];
    }
#pragma unroll
    for (int o = 16; o > 0; o >>= 1) {
        s  += __shfl_xor_sync(0xffffffffu, s, o);
        sq += __shfl_xor_sync(0xffffffffu, sq, o);
    }
    __shared__ float ws[4], wq[4];
    __shared__ float mean_s, inv_s;
    const int warp = threadIdx.x >> 5, lane = threadIdx.x & 31;
    if (lane == 0) { ws[warp] = s; wq[warp] = sq; }
    __syncthreads();
    if (threadIdx.x == 0) {
        float S = ws[0] + ws[1] + ws[2] + ws[3];
        float Q = wq[0] + wq[1] + wq[2] + wq[3];
        float mean = S * (1.0f / cfg::Din);
        float var  = Q * (1.0f / cfg::Din) - mean * mean;
        mean_s = mean;
        inv_s  = rsqrtf(var + 1e-5f);
    }
    __syncthreads();
    float* po = out + (size_t)row * cfg::Din;
    float* pt = out_t + (size_t)row * cfg::Din;
#pragma unroll
    for (int i = 0; i < 4; i++) {
        int c = threadIdx.x + i * 128;
        float r = (v[i] - mean_s) * inv_s;
        po[c] = r;
        if (T32) pt[c] = f2tf_f(r);
    }
}

// ---------------------------------------------------------------------------
// kernel_launch
// ---------------------------------------------------------------------------
extern "C" void kernel_launch(void* const* d_in, const int* in_sizes, int n_in,
                              void* d_out, int out_size)
{
    const float* query = (const float*)d_in[0];
    const float* key   = (const float*)d_in[1];
    const float* value = (const float*)d_in[2];
    const float* mask  = (const float*)d_in[3];
    const float* WQ    = (const float*)d_in[4];
    const float* WK    = (const float*)d_in[5];
    const float* WV    = (const float*)d_in[6];
    const float* WO    = (const float*)d_in[7];
    const float* W1    = (const float*)d_in[8];
    const float* W2    = (const float*)d_in[9];
    float* out = (float*)d_out;

    float *Qd, *Kd, *Vd, *attn, *proj, *h1, *h1t, *mid, *ff;
    float *qt, *kt, *vt, *WQt, *WKt, *WVt, *WOt, *W1t, *W2t;
    cudaGetSymbolAddress((void**)&Qd,   g_Q);
    cudaGetSymbolAddress((void**)&Kd,   g_K);
    cudaGetSymbolAddress((void**)&Vd,   g_V);
    cudaGetSymbolAddress((void**)&attn, g_attn);
    cudaGetSymbolAddress((void**)&proj, g_proj);
    cudaGetSymbolAddress((void**)&h1,   g_h1);
    cudaGetSymbolAddress((void**)&h1t,  g_h1t);
    cudaGetSymbolAddress((void**)&mid,  g_mid);
    cudaGetSymbolAddress((void**)&ff,   g_ff);
    cudaGetSymbolAddress((void**)&qt,   g_qt);
    cudaGetSymbolAddress((void**)&kt,   g_kt);
    cudaGetSymbolAddress((void**)&vt,   g_vt);
    cudaGetSymbolAddress((void**)&WQt,  g_WQt);
    cudaGetSymbolAddress((void**)&WKt,  g_WKt);
    cudaGetSymbolAddress((void**)&WVt,  g_WVt);
    cudaGetSymbolAddress((void**)&WOt,  g_WOt);
    cudaGetSymbolAddress((void**)&W1t,  g_W1t);
    cudaGetSymbolAddress((void**)&W2t,  g_W2t);

    cudaFuncSetAttribute(flash2_kernel, cudaFuncAttributeMaxDynamicSharedMemorySize,
                         (int)FLASH2_SMEM);
    cudaFuncSetAttribute(gemm_tf32<0>, cudaFuncAttributeMaxDynamicSharedMemorySize,
                         (int)GEMM_SMEM);
    cudaFuncSetAttribute(gemm_tf32<3>, cudaFuncAttributeMaxDynamicSharedMemorySize,
                         (int)GEMM_SMEM);
    cudaFuncSetAttribute(gemm_qkv, cudaFuncAttributeMaxDynamicSharedMemorySize,
                         (int)GEMM_SMEM);

    // -- one-launch tf32 truncation of raw inputs + weights --
    const int nIn = cfg::Mtok * cfg::Din;      // 4,194,304
    const int nWs = cfg::Din * cfg::Din;       // 262,144
    const int nWf = cfg::Din * cfg::Dmid;      // 1,048,576
    Cvt9 cv;
    cv.s[0] = query; cv.d[0] = qt;  cv.n[0] = nIn;
    cv.s[1] = key;   cv.d[1] = kt;  cv.n[1] = nIn;
    cv.s[2] = value; cv.d[2] = vt;  cv.n[2] = nIn;
    cv.s[3] = WQ;    cv.d[3] = WQt; cv.n[3] = nWs;
    cv.s[4] = WK;    cv.d[4] = WKt; cv.n[4] = nWs;
    cv.s[5] = WV;    cv.d[5] = WVt; cv.n[5] = nWs;
    cv.s[6] = WO;    cv.d[6] = WOt; cv.n[6] = nWs;
    cv.s[7] = W1;    cv.d[7] = W1t; cv.n[7] = nWf;
    cv.s[8] = W2;    cv.d[8] = W2t; cv.n[8] = nWf;
    cvt_all_kernel<<<2048, 256>>>(cv);

    const dim3 gProj(cfg::Din / BN, cfg::Mtok / BM);        // (4, 64)
    const dim3 gQkv (cfg::Din / BN, cfg::Mtok / BM, 3);     // (4, 64, 3)
    const dim3 gFfn1(cfg::Dmid / BN, cfg::Mtok / BM);       // (16, 64)

    // Fused QKV projections (head-split + tf32 epilogue)
    gemm_qkv<<<gQkv, 256, GEMM_SMEM>>>(qt, kt, vt, WQt, WKt, WVt, Qd, Kd, Vd);

    // Flash attention (consumes tf32 Q/K/V, emits tf32 attn)
    dim3 gFlash(cfg::Ls / FQ2, cfg::Hh, cfg::Bb);           // (16, 8, 4)
    flash2_kernel<<<gFlash, 256, FLASH2_SMEM>>>(Qd, Kd, Vd, mask, attn);

    // Output projection + residual LN (fp32 out + tf32 copy for FFN1)
    gemm_tf32<0><<<gProj, 256, GEMM_SMEM>>>(attn, WOt, proj, cfg::Mtok, cfg::Din, cfg::Din);
    ln_add_kernel<true><<<cfg::Mtok, 128>>>(query, proj, h1, h1t);

    // FFN (FFN1: relu + tf32 epilogue; FFN2: fp32)
    gemm_tf32<3><<<gFfn1, 256, GEMM_SMEM>>>(h1t, W1t, mid, cfg::Mtok, cfg::Dmid, cfg::Din);
    gemm_tf32<0><<<gProj, 256, GEMM_SMEM>>>(mid, W2t, ff, cfg::Mtok, cfg::Din, cfg::Dmid);
    ln_add_kernel<false><<<cfg::Mtok, 128>>>(h1, ff, out, out);

    (void)in_sizes; (void)n_in; (void)out_size;
}